// round 1
// baseline (speedup 1.0000x reference)
#include <cuda_runtime.h>
#include <cuda_bf16.h>
#include <math.h>

// Problem constants (fixed by the dataset)
#define MAXN 100000
#define MAXE 320000
#define DD   256

// ---------------- scratch (device globals; no allocs allowed) ----------------
__device__ float g_S0[(size_t)MAXN * 512];
__device__ float g_S1[(size_t)MAXN * 512];
__device__ float g_M [(size_t)MAXN * 512];
__device__ float g_SAVE[(size_t)MAXN * DD];

__device__ float g_WteI[6 * 4 * 512 * 256];    // transposed inner edge W: [l][t][K=512][dout=256]
__device__ float g_WteO[2 * 4 * 1024 * 512];   // transposed out edge W:   [b][t][K=1024][dout=512]
__device__ float g_WtdI[6 * 256 * 256];        // transposed inner dense W: [l][K=256][dout=256]
__device__ float g_WtdO[2 * 512 * 256];        // transposed out dense W:   [b][K=512][dout=256]

__device__ int g_typeEdges[MAXE];
__device__ int g_cnt[4];
__device__ int g_off[4];
__device__ int g_cur[4];

// ---------------- small utility kernels ----------------
__global__ void clear_f4_kernel(float4* p, long long n4) {
    long long i = (long long)blockIdx.x * blockDim.x + threadIdx.x;
    long long stride = (long long)gridDim.x * blockDim.x;
    float4 z = make_float4(0.f, 0.f, 0.f, 0.f);
    for (; i < n4; i += stride) p[i] = z;
}

__global__ void clear_counts_kernel() {
    int i = threadIdx.x;
    if (i < 4) { g_cnt[i] = 0; g_cur[i] = 0; }
}

__global__ void count_types_kernel(const int* __restrict__ etype, int E) {
    int e = blockIdx.x * blockDim.x + threadIdx.x;
    if (e < E) atomicAdd(&g_cnt[etype[e] - 1], 1);
}

__global__ void offsets_kernel() {
    if (threadIdx.x == 0) {
        g_off[0] = 0;
        g_off[1] = g_cnt[0];
        g_off[2] = g_cnt[0] + g_cnt[1];
        g_off[3] = g_cnt[0] + g_cnt[1] + g_cnt[2];
    }
}

__global__ void scatter_types_kernel(const int* __restrict__ etype, int E) {
    int e = blockIdx.x * blockDim.x + threadIdx.x;
    if (e < E) {
        int t = etype[e] - 1;
        int p = atomicAdd(&g_cur[t], 1);
        g_typeEdges[g_off[t] + p] = e;
    }
}

// transpose: in [mat][R][C] -> out [mat][C][R]
__global__ void transpose_kernel(const float* __restrict__ in, float* __restrict__ out,
                                 int R, int C) {
    __shared__ float tile[32][33];
    int mat = blockIdx.z;
    const float* pin  = in  + (size_t)mat * R * C;
    float*       pout = out + (size_t)mat * R * C;
    int c  = blockIdx.x * 32 + threadIdx.x;
    int r0 = blockIdx.y * 32;
    #pragma unroll
    for (int i = threadIdx.y; i < 32; i += 8) {
        int r = r0 + i;
        if (r < R && c < C) tile[i][threadIdx.x] = pin[(size_t)r * C + c];
    }
    __syncthreads();
    int rr = r0 + threadIdx.x;
    int cc = blockIdx.x * 32;
    #pragma unroll
    for (int i = threadIdx.y; i < 32; i += 8) {
        int c2 = cc + i;
        if (c2 < C && rr < R) pout[(size_t)c2 * R + rr] = tile[threadIdx.x][i];
    }
}

__global__ void embed_kernel(const float4* __restrict__ tab, const int* __restrict__ ids,
                             float4* __restrict__ outS, int N) {
    int idx = blockIdx.x * blockDim.x + threadIdx.x;  // units of float4, 64 per row
    if (idx >= N * 64) return;
    int node = idx >> 6, c = idx & 63;
    int r = ids[node];
    outS[(size_t)node * 64 + c] = tab[(size_t)r * 64 + c];
}

__global__ void copy256_kernel(const float4* __restrict__ src, float4* __restrict__ dst, int N) {
    int idx = blockIdx.x * blockDim.x + threadIdx.x;
    if (idx < N * 64) dst[idx] = src[idx];
}

// res[v] = [save[v] (256), x[v] (256)] -> 512-wide
__global__ void concat_kernel(const float4* __restrict__ save, const float4* __restrict__ x,
                              float4* __restrict__ res, int N) {
    int idx = blockIdx.x * blockDim.x + threadIdx.x;  // float4 units over [N][128]
    if (idx >= N * 128) return;
    int node = idx >> 7, c = idx & 127;
    float4 v = (c < 64) ? save[(size_t)node * 64 + c] : x[(size_t)node * 64 + (c - 64)];
    res[(size_t)node * 128 + c] = v;
}

// ---------------- gelu + layernorm (in place on M), one warp per node ----------------
__global__ void gelu_ln_kernel(float* __restrict__ M, const float* __restrict__ s,
                               const float* __restrict__ b, int dm, int N) {
    int warp = (blockIdx.x * blockDim.x + threadIdx.x) >> 5;
    int lane = threadIdx.x & 31;
    if (warp >= N) return;
    float* row = M + (size_t)warp * dm;
    int per = dm >> 5;  // 8 or 16
    float v[16];
    float sum = 0.f;
    for (int i = 0; i < per; i++) {
        float x = row[i * 32 + lane];
        float g = 0.5f * x * (1.0f + erff(x * 0.70710678118654752f));
        v[i] = g; sum += g;
    }
    #pragma unroll
    for (int o = 16; o > 0; o >>= 1) sum += __shfl_xor_sync(0xFFFFFFFF, sum, o);
    float mu = sum / (float)dm;
    float vs = 0.f;
    for (int i = 0; i < per; i++) { float d = v[i] - mu; vs += d * d; }
    #pragma unroll
    for (int o = 16; o > 0; o >>= 1) vs += __shfl_xor_sync(0xFFFFFFFF, vs, o);
    float inv = rsqrtf(vs / (float)dm + 1e-5f);
    for (int i = 0; i < per; i++) {
        int c = i * 32 + lane;
        row[c] = (v[i] - mu) * inv * s[c] + b[c];
    }
}

// ---------------- GEMM kernels ----------------
#define BM 128
#define BN 128
#define BKK 16

// Edge GEMM: per type t, rows = type-t edges, A[e][k] = S[src|tgt][...], B = Wt[t]
// Scatter-adds the output into Mout[tgt].
__global__ __launch_bounds__(256, 2)
void edge_gemm_kernel(const float* __restrict__ S, int din,
                      const float* __restrict__ Wt,      // [4][2*din][din]
                      float* __restrict__ Mout,
                      const int* __restrict__ src,
                      const int* __restrict__ tgt) {
    int t = blockIdx.y;
    int cnt = g_cnt[t];
    int row0 = blockIdx.x * BM;
    if (row0 >= cnt) return;
    int off  = g_off[t];
    int col0 = blockIdx.z * BN;
    int dout = din;
    int K = 2 * din;
    const float* W = Wt + (size_t)t * K * dout;

    __shared__ float As[BKK][BM + 4];
    __shared__ float Bs[BKK][BN];
    __shared__ int sSrc[BM];
    __shared__ int sTgt[BM];

    int tid = threadIdx.x;
    for (int m = tid; m < BM; m += 256) {
        int r = row0 + m;
        int sn = 0, tn = -1;
        if (r < cnt) { int e = g_typeEdges[off + r]; sn = src[e]; tn = tgt[e]; }
        sSrc[m] = sn; sTgt[m] = tn;
    }
    __syncthreads();

    float acc[8][8];
    #pragma unroll
    for (int i = 0; i < 8; i++)
        #pragma unroll
        for (int j = 0; j < 8; j++) acc[i][j] = 0.f;

    int tx = tid & 15, ty = tid >> 4;

    for (int kt = 0; kt < K; kt += BKK) {
        // A: 128x16 gathered, 2 float4 per thread
        #pragma unroll
        for (int i = 0; i < 2; i++) {
            int slot = tid + i * 256;         // 0..511
            int m = slot >> 2, kg = slot & 3;
            int gk = kt + kg * 4;
            int node, c;
            if (gk < din) { node = sSrc[m]; c = gk; }
            else          { node = sTgt[m]; if (node < 0) node = 0; c = gk - din; }
            float4 v = *(const float4*)(S + (size_t)node * din + c);
            As[kg * 4 + 0][m] = v.x; As[kg * 4 + 1][m] = v.y;
            As[kg * 4 + 2][m] = v.z; As[kg * 4 + 3][m] = v.w;
        }
        // B: 16x128
        #pragma unroll
        for (int i = 0; i < 2; i++) {
            int slot = tid + i * 256;
            int k = slot >> 5, n = (slot & 31) * 4;
            float4 v = *(const float4*)(W + (size_t)(kt + k) * dout + col0 + n);
            *(float4*)&Bs[k][n] = v;
        }
        __syncthreads();
        #pragma unroll
        for (int k = 0; k < BKK; k++) {
            float a[8], bb[8];
            *(float4*)&a[0]  = *(const float4*)&As[k][ty * 8];
            *(float4*)&a[4]  = *(const float4*)&As[k][ty * 8 + 4];
            *(float4*)&bb[0] = *(const float4*)&Bs[k][tx * 8];
            *(float4*)&bb[4] = *(const float4*)&Bs[k][tx * 8 + 4];
            #pragma unroll
            for (int i = 0; i < 8; i++)
                #pragma unroll
                for (int j = 0; j < 8; j++) acc[i][j] += a[i] * bb[j];
        }
        __syncthreads();
    }

    #pragma unroll
    for (int i = 0; i < 8; i++) {
        int m = ty * 8 + i;
        int v = sTgt[m];
        if (v < 0) continue;
        float* dst = Mout + (size_t)v * dout + col0 + tx * 8;
        #pragma unroll
        for (int j = 0; j < 8; j++) atomicAdd(dst + j, acc[i][j]);
    }
}

// Dense GEMM: Out[m] = tanh(A[m] @ Wt + bias). A: [Nrows][K], Wt: [K][dout]
__global__ __launch_bounds__(256, 2)
void dense_gemm_kernel(const float* __restrict__ A, int Nrows, int K,
                       const float* __restrict__ Wt,
                       const float* __restrict__ bias,
                       float* __restrict__ Out, int dout) {
    int row0 = blockIdx.x * BM;
    int col0 = blockIdx.z * BN;

    __shared__ float As[BKK][BM + 4];
    __shared__ float Bs[BKK][BN];

    int tid = threadIdx.x;
    int tx = tid & 15, ty = tid >> 4;

    float acc[8][8];
    #pragma unroll
    for (int i = 0; i < 8; i++)
        #pragma unroll
        for (int j = 0; j < 8; j++) acc[i][j] = 0.f;

    for (int kt = 0; kt < K; kt += BKK) {
        #pragma unroll
        for (int i = 0; i < 2; i++) {
            int slot = tid + i * 256;
            int m = slot >> 2, kg = slot & 3;
            int r = row0 + m;
            int rr = (r < Nrows) ? r : 0;
            float4 v = *(const float4*)(A + (size_t)rr * K + kt + kg * 4);
            As[kg * 4 + 0][m] = v.x; As[kg * 4 + 1][m] = v.y;
            As[kg * 4 + 2][m] = v.z; As[kg * 4 + 3][m] = v.w;
        }
        #pragma unroll
        for (int i = 0; i < 2; i++) {
            int slot = tid + i * 256;
            int k = slot >> 5, n = (slot & 31) * 4;
            float4 v = *(const float4*)(Wt + (size_t)(kt + k) * dout + col0 + n);
            *(float4*)&Bs[k][n] = v;
        }
        __syncthreads();
        #pragma unroll
        for (int k = 0; k < BKK; k++) {
            float a[8], bb[8];
            *(float4*)&a[0]  = *(const float4*)&As[k][ty * 8];
            *(float4*)&a[4]  = *(const float4*)&As[k][ty * 8 + 4];
            *(float4*)&bb[0] = *(const float4*)&Bs[k][tx * 8];
            *(float4*)&bb[4] = *(const float4*)&Bs[k][tx * 8 + 4];
            #pragma unroll
            for (int i = 0; i < 8; i++)
                #pragma unroll
                for (int j = 0; j < 8; j++) acc[i][j] += a[i] * bb[j];
        }
        __syncthreads();
    }

    #pragma unroll
    for (int i = 0; i < 8; i++) {
        int m = row0 + ty * 8 + i;
        if (m >= Nrows) continue;
        int c = col0 + tx * 8;
        float4 o0, o1;
        o0.x = tanhf(acc[i][0] + bias[c + 0]);
        o0.y = tanhf(acc[i][1] + bias[c + 1]);
        o0.z = tanhf(acc[i][2] + bias[c + 2]);
        o0.w = tanhf(acc[i][3] + bias[c + 3]);
        o1.x = tanhf(acc[i][4] + bias[c + 4]);
        o1.y = tanhf(acc[i][5] + bias[c + 5]);
        o1.z = tanhf(acc[i][6] + bias[c + 6]);
        o1.w = tanhf(acc[i][7] + bias[c + 7]);
        *(float4*)(Out + (size_t)m * dout + c)     = o0;
        *(float4*)(Out + (size_t)m * dout + c + 4) = o1;
    }
}

// ---------------- host-side driver ----------------
static void get_ptrs(float** pS0, float** pS1, float** pM, float** pSave,
                     float** pWteI, float** pWteO, float** pWtdI, float** pWtdO) {
    cudaGetSymbolAddress((void**)pS0,   g_S0);
    cudaGetSymbolAddress((void**)pS1,   g_S1);
    cudaGetSymbolAddress((void**)pM,    g_M);
    cudaGetSymbolAddress((void**)pSave, g_SAVE);
    cudaGetSymbolAddress((void**)pWteI, g_WteI);
    cudaGetSymbolAddress((void**)pWteO, g_WteO);
    cudaGetSymbolAddress((void**)pWtdI, g_WtdI);
    cudaGetSymbolAddress((void**)pWtdO, g_WtdO);
}

static void run_gnn_layer(const float* Sin, int din, int N, int E,
                          const float* Wt_edge, const float* ls, const float* lb,
                          const float* Wt_dense, const float* bias,
                          float* dest, float* Mbuf,
                          const int* src, const int* tgt) {
    // clear M
    long long n4 = (long long)N * din / 4;
    clear_f4_kernel<<<4096, 256>>>((float4*)Mbuf, n4);
    // edge GEMMs (all 4 types), atomics into M
    dim3 egrid((E + BM - 1) / BM, 4, din / BN);
    edge_gemm_kernel<<<egrid, 256>>>(Sin, din, Wt_edge, Mbuf, src, tgt);
    // gelu + layernorm in place
    int warps_per_block = 8;
    gelu_ln_kernel<<<(N + warps_per_block - 1) / warps_per_block, 256>>>(Mbuf, ls, lb, din, N);
    // dense + tanh
    dim3 dgrid((N + BM - 1) / BM, 1, 256 / BN);
    dense_gemm_kernel<<<dgrid, 256>>>(Mbuf, N, din, Wt_dense, bias, dest, 256);
}

extern "C" void kernel_launch(void* const* d_in, const int* in_sizes, int n_in,
                              void* d_out, int out_size) {
    const int*   ids   = (const int*)d_in[0];
    const int*   te    = (const int*)d_in[1];
    const float* embed = (const float*)d_in[2];
    const float* WeI   = (const float*)d_in[3];
    const float* lsI   = (const float*)d_in[4];
    const float* lbI   = (const float*)d_in[5];
    const float* WdI   = (const float*)d_in[6];
    const float* bdI   = (const float*)d_in[7];
    const float* WeO   = (const float*)d_in[8];
    const float* lsO   = (const float*)d_in[9];
    const float* lbO   = (const float*)d_in[10];
    const float* WdO   = (const float*)d_in[11];
    const float* bdO   = (const float*)d_in[12];
    float* out = (float*)d_out;

    int N = in_sizes[0];
    int E = in_sizes[1] / 3;
    const int* etype = te;
    const int* src   = te + E;
    const int* tgt   = te + 2 * E;

    float *S0, *S1, *M, *SAVE, *WteI, *WteO, *WtdI, *WtdO;
    get_ptrs(&S0, &S1, &M, &SAVE, &WteI, &WteO, &WtdI, &WtdO);

    // --- preprocessing ---
    clear_counts_kernel<<<1, 32>>>();
    count_types_kernel<<<(E + 255) / 256, 256>>>(etype, E);
    offsets_kernel<<<1, 1>>>();
    scatter_types_kernel<<<(E + 255) / 256, 256>>>(etype, E);

    transpose_kernel<<<dim3(16, 8, 24),  dim3(32, 8)>>>(WeI, WteI, 256, 512);
    transpose_kernel<<<dim3(32, 16, 8),  dim3(32, 8)>>>(WeO, WteO, 512, 1024);
    transpose_kernel<<<dim3(8, 8, 6),    dim3(32, 8)>>>(WdI, WtdI, 256, 256);
    transpose_kernel<<<dim3(16, 8, 2),   dim3(32, 8)>>>(WdO, WtdO, 256, 512);

    // --- embedding ---
    embed_kernel<<<(N * 64 + 255) / 256, 256>>>((const float4*)embed, ids, (float4*)S0, N);

    float* S = S0;
    float* Snext = S1;

    for (int b = 0; b < 2; b++) {
        // save block-start state
        copy256_kernel<<<(N * 64 + 255) / 256, 256>>>((const float4*)S, (float4*)SAVE, N);
        // 3 inner layers (din = 256)
        for (int i = 0; i < 3; i++) {
            int l = 3 * b + i;
            run_gnn_layer(S, 256, N, E,
                          WteI + (size_t)l * 4 * 512 * 256,
                          lsI + (size_t)l * 256, lbI + (size_t)l * 256,
                          WtdI + (size_t)l * 256 * 256, bdI + (size_t)l * 256,
                          Snext, M, src, tgt);
            float* tmp = S; S = Snext; Snext = tmp;
        }
        // concat [SAVE, S] -> Snext (512-wide)
        concat_kernel<<<(N * 128 + 255) / 256, 256>>>((const float4*)SAVE, (const float4*)S,
                                                      (float4*)Snext, N);
        { float* tmp = S; S = Snext; Snext = tmp; }
        // output layer (din = 512)
        float* dest = (b == 1) ? out : Snext;
        run_gnn_layer(S, 512, N, E,
                      WteO + (size_t)b * 4 * 1024 * 512,
                      lsO + (size_t)b * 512, lbO + (size_t)b * 512,
                      WtdO + (size_t)b * 512 * 256, bdO + (size_t)b * 256,
                      dest, M, src, tgt);
        if (b == 0) { float* tmp = S; S = Snext; Snext = tmp; }
    }
}

// round 3
// speedup vs baseline: 1.8659x; 1.8659x over previous
#include <cuda_runtime.h>
#include <cuda_bf16.h>
#include <math.h>
#include <stdint.h>

#define MAXN 100000
#define MAXE 320000

// ---------------- scratch (device globals; no allocs allowed) ----------------
__device__ __align__(16) float g_S0[(size_t)MAXN * 512];
__device__ __align__(16) float g_S1[(size_t)MAXN * 512];
__device__ __align__(16) float g_M [(size_t)MAXN * 512];
__device__ __align__(16) float g_SAVE[(size_t)MAXN * 256];

// bf16 hi/lo weight splits (natural [dout][K] layout == col-major B for mma.row.col)
__device__ __align__(16) __nv_bfloat16 g_WeI_h[6 * 4 * 256 * 512],  g_WeI_l[6 * 4 * 256 * 512];
__device__ __align__(16) __nv_bfloat16 g_WeO_h[2 * 4 * 512 * 1024], g_WeO_l[2 * 4 * 512 * 1024];
__device__ __align__(16) __nv_bfloat16 g_WdI_h[6 * 256 * 256],      g_WdI_l[6 * 256 * 256];
__device__ __align__(16) __nv_bfloat16 g_WdO_h[2 * 256 * 512],      g_WdO_l[2 * 256 * 512];

__device__ int g_typeEdges[MAXE];
__device__ int g_cnt[4], g_off[4], g_cur[4];

// ---------------- helpers ----------------
__device__ __forceinline__ uint32_t smem_u32(const void* p) {
    uint32_t a;
    asm("{ .reg .u64 t; cvta.to.shared.u64 t, %1; cvt.u32.u64 %0, t; }" : "=r"(a) : "l"(p));
    return a;
}

__device__ __forceinline__ void ldm_x4(uint32_t addr, uint32_t r[4]) {
    asm volatile("ldmatrix.sync.aligned.m8n8.x4.shared.b16 {%0,%1,%2,%3}, [%4];"
                 : "=r"(r[0]), "=r"(r[1]), "=r"(r[2]), "=r"(r[3]) : "r"(addr));
}

__device__ __forceinline__ void mma16816(float c[4], const uint32_t a[4], const uint32_t b[2]) {
    asm volatile(
        "mma.sync.aligned.m16n8k16.row.col.f32.bf16.bf16.f32 "
        "{%0,%1,%2,%3}, {%4,%5,%6,%7}, {%8,%9}, {%0,%1,%2,%3};"
        : "+f"(c[0]), "+f"(c[1]), "+f"(c[2]), "+f"(c[3])
        : "r"(a[0]), "r"(a[1]), "r"(a[2]), "r"(a[3]), "r"(b[0]), "r"(b[1]));
}

__device__ __forceinline__ uint32_t pk_hi(float a, float b) {
    __nv_bfloat162 t = __floats2bfloat162_rn(a, b);
    return reinterpret_cast<uint32_t&>(t);
}
__device__ __forceinline__ float bf_rt(float a) {
    return __bfloat162float(__float2bfloat16(a));
}

// ---------------- small utility kernels ----------------
__global__ void clear_f4_kernel(float4* p, long long n4) {
    long long i = (long long)blockIdx.x * blockDim.x + threadIdx.x;
    long long stride = (long long)gridDim.x * blockDim.x;
    float4 z = make_float4(0.f, 0.f, 0.f, 0.f);
    for (; i < n4; i += stride) p[i] = z;
}

__global__ void clear_counts_kernel() {
    int i = threadIdx.x;
    if (i < 4) { g_cnt[i] = 0; g_cur[i] = 0; }
}

__global__ void count_types_kernel(const int* __restrict__ etype, int E) {
    int e = blockIdx.x * blockDim.x + threadIdx.x;
    if (e < E) atomicAdd(&g_cnt[etype[e] - 1], 1);
}

__global__ void offsets_kernel() {
    if (threadIdx.x == 0) {
        g_off[0] = 0;
        g_off[1] = g_cnt[0];
        g_off[2] = g_cnt[0] + g_cnt[1];
        g_off[3] = g_cnt[0] + g_cnt[1] + g_cnt[2];
    }
}

__global__ void scatter_types_kernel(const int* __restrict__ etype, int E) {
    int e = blockIdx.x * blockDim.x + threadIdx.x;
    if (e < E) {
        int t = etype[e] - 1;
        int p = atomicAdd(&g_cur[t], 1);
        g_typeEdges[g_off[t] + p] = e;
    }
}

__global__ void conv_bf16_kernel(const float* __restrict__ w, __nv_bfloat16* __restrict__ hi,
                                 __nv_bfloat16* __restrict__ lo, int n) {
    int i = blockIdx.x * blockDim.x + threadIdx.x;
    if (i >= n) return;
    float x = w[i];
    __nv_bfloat16 h = __float2bfloat16(x);
    hi[i] = h;
    lo[i] = __float2bfloat16(x - __bfloat162float(h));
}

__global__ void embed_kernel(const float4* __restrict__ tab, const int* __restrict__ ids,
                             float4* __restrict__ outS, int N) {
    int idx = blockIdx.x * blockDim.x + threadIdx.x;
    if (idx >= N * 64) return;
    int node = idx >> 6, c = idx & 63;
    int r = ids[node];
    outS[(size_t)node * 64 + c] = tab[(size_t)r * 64 + c];
}

__global__ void copy256_kernel(const float4* __restrict__ src, float4* __restrict__ dst, int N) {
    int idx = blockIdx.x * blockDim.x + threadIdx.x;
    if (idx < N * 64) dst[idx] = src[idx];
}

__global__ void concat_kernel(const float4* __restrict__ save, const float4* __restrict__ x,
                              float4* __restrict__ res, int N) {
    int idx = blockIdx.x * blockDim.x + threadIdx.x;
    if (idx >= N * 128) return;
    int node = idx >> 7, c = idx & 127;
    float4 v = (c < 64) ? save[(size_t)node * 64 + c] : x[(size_t)node * 64 + (c - 64)];
    res[(size_t)node * 128 + c] = v;
}

__global__ void gelu_ln_kernel(float* __restrict__ M, const float* __restrict__ s,
                               const float* __restrict__ b, int dm, int N) {
    int warp = (blockIdx.x * blockDim.x + threadIdx.x) >> 5;
    int lane = threadIdx.x & 31;
    if (warp >= N) return;
    float* row = M + (size_t)warp * dm;
    int per = dm >> 5;
    float v[16];
    float sum = 0.f;
    for (int i = 0; i < per; i++) {
        float x = row[i * 32 + lane];
        float g = 0.5f * x * (1.0f + erff(x * 0.70710678118654752f));
        v[i] = g; sum += g;
    }
    #pragma unroll
    for (int o = 16; o > 0; o >>= 1) sum += __shfl_xor_sync(0xFFFFFFFF, sum, o);
    float mu = sum / (float)dm;
    float vs = 0.f;
    for (int i = 0; i < per; i++) { float d = v[i] - mu; vs += d * d; }
    #pragma unroll
    for (int o = 16; o > 0; o >>= 1) vs += __shfl_xor_sync(0xFFFFFFFF, vs, o);
    float inv = rsqrtf(vs / (float)dm + 1e-5f);
    for (int i = 0; i < per; i++) {
        int c = i * 32 + lane;
        row[c] = (v[i] - mu) * inv * s[c] + b[c];
    }
}

// ---------------- mma.sync GEMM (MODE 0: edge gather+scatter, MODE 1: dense+tanh) ----------------
// CTA tile 128x128, K chunk 32 bf16, bf16x3 split (hh + hl + lh).
// SMEM stage 40960B: A_hi[128][40] A_lo B_hi B_lo (80B padded rows). Double buffered.

#define ROWB 80            // bytes per padded row (40 bf16)
#define SPLIT_OFF 10240    // 128 * 80
#define BOFF 20480
#define STAGE 40960
#define SMEM_BYTES (1024 + 2 * STAGE)

template<int MODE>
__global__ __launch_bounds__(256, 2)
void mma_gemm(const float* __restrict__ A, int strideA, int K,
              const __nv_bfloat16* __restrict__ Bh_, const __nv_bfloat16* __restrict__ Bl_,
              int dout, float* __restrict__ Out,
              const int* __restrict__ src, const int* __restrict__ tgt,
              const float* __restrict__ bias, int Nrows) {
    extern __shared__ char smem[];
    int tid = threadIdx.x;
    int wid = tid >> 5, lane = tid & 31;
    int row0 = blockIdx.x * 128;
    int col0 = blockIdx.z * 128;

    const __nv_bfloat16 *Bh, *Bl;
    int cnt = 0, offT = 0;
    if (MODE == 0) {
        int t = blockIdx.y;
        cnt = g_cnt[t];
        if (row0 >= cnt) return;
        offT = g_off[t];
        Bh = Bh_ + (size_t)t * dout * K;
        Bl = Bl_ + (size_t)t * dout * K;
    } else {
        if (row0 >= Nrows) return;
        Bh = Bh_; Bl = Bl_;
    }

    int* sSrc = (int*)smem;
    int* sTgt = (int*)(smem + 512);
    char* tiles = smem + 1024;

    if (MODE == 0 && tid < 128) {
        int r = row0 + tid;
        int sn = 0, tn = -1;
        if (r < cnt) { int e = g_typeEdges[offT + r]; sn = src[e]; tn = tgt[e]; }
        sSrc[tid] = sn; sTgt[tid] = tn;
    }
    __syncthreads();

    // ---- ldmatrix base addresses (byte offsets into stage) ----
    uint32_t sb = smem_u32(tiles);
    int warp_m = wid >> 2, warp_n = wid & 3;
    uint32_t aAddr[4], bAddr[2];
    {
        int r = (lane & 15), hi8 = (lane >> 4) & 1;
        #pragma unroll
        for (int mt = 0; mt < 4; mt++)
            aAddr[mt] = sb + (warp_m * 64 + mt * 16 + r) * ROWB + hi8 * 16;
        int nr = hi8 * 8 + (lane & 7), kq = (lane >> 3) & 1;
        #pragma unroll
        for (int g = 0; g < 2; g++)
            bAddr[g] = sb + BOFF + (warp_n * 32 + g * 16 + nr) * ROWB + kq * 16;
    }

    float acc[4][4][4];
    #pragma unroll
    for (int i = 0; i < 4; i++)
        #pragma unroll
        for (int j = 0; j < 4; j++)
            #pragma unroll
            for (int q = 0; q < 4; q++) acc[i][j][q] = 0.f;

    const int nch = K >> 5;

    // ---- chunk loader: gather A (fp32 -> bf16 hi/lo), copy B hi/lo ----
    auto load_chunk = [&](int c) {
        int kt = c * 32;
        char* stg = tiles + (c & 1) * STAGE;
        bool useSrc = true; int colb = kt;
        if (MODE == 0) { useSrc = kt < strideA; colb = useSrc ? kt : kt - strideA; }
        #pragma unroll
        for (int i = 0; i < 4; i++) {
            int slot = tid + i * 256;          // 0..1023
            int m = slot >> 3, f = slot & 7;
            const float* rowp;
            if (MODE == 0) {
                int node = useSrc ? sSrc[m] : sTgt[m];
                if (node < 0) node = 0;
                rowp = A + (size_t)node * strideA + colb;
            } else {
                int r = row0 + m;
                if (r >= Nrows) r = 0;
                rowp = A + (size_t)r * K + colb;
            }
            float4 v = *(const float4*)(rowp + f * 4);
            uint32_t h0 = pk_hi(v.x, v.y), h1 = pk_hi(v.z, v.w);
            uint32_t l0 = pk_hi(v.x - bf_rt(v.x), v.y - bf_rt(v.y));
            uint32_t l1 = pk_hi(v.z - bf_rt(v.z), v.w - bf_rt(v.w));
            uint32_t off = m * ROWB + f * 8;
            *(uint2*)(stg + off)             = make_uint2(h0, h1);
            *(uint2*)(stg + SPLIT_OFF + off) = make_uint2(l0, l1);
        }
        #pragma unroll
        for (int i = 0; i < 4; i++) {
            int slot = tid + i * 256;          // 0..1023
            int split = slot >> 9, s2 = slot & 511;
            int n = s2 >> 2, u = s2 & 3;
            const __nv_bfloat16* bs = split ? Bl : Bh;
            uint4 v = *(const uint4*)(bs + (size_t)(col0 + n) * K + kt + u * 8);
            *(uint4*)(stg + BOFF + split * SPLIT_OFF + n * ROWB + u * 16) = v;
        }
    };

    load_chunk(0);
    __syncthreads();

    for (int c = 0; c < nch; c++) {
        if (c + 1 < nch) load_chunk(c + 1);
        uint32_t stoff = (c & 1) * STAGE;
        #pragma unroll
        for (int ks = 0; ks < 2; ks++) {
            uint32_t ko = stoff + ks * 32;     // 16 bf16 = 32 bytes
            uint32_t bh[2][4], bl[2][4];       // [g][4 regs] = b frags for n8 groups 2g,2g+1
            ldm_x4(bAddr[0] + ko, bh[0]);
            ldm_x4(bAddr[1] + ko, bh[1]);
            ldm_x4(bAddr[0] + ko + SPLIT_OFF, bl[0]);
            ldm_x4(bAddr[1] + ko + SPLIT_OFF, bl[1]);
            #pragma unroll
            for (int mt = 0; mt < 4; mt++) {
                uint32_t ah[4], al[4];
                ldm_x4(aAddr[mt] + ko, ah);
                ldm_x4(aAddr[mt] + ko + SPLIT_OFF, al);
                #pragma unroll
                for (int nt = 0; nt < 4; nt++) {
                    const uint32_t* ph = &bh[nt >> 1][(nt & 1) * 2];
                    const uint32_t* pl = &bl[nt >> 1][(nt & 1) * 2];
                    mma16816(acc[mt][nt], ah, ph);
                    mma16816(acc[mt][nt], ah, pl);
                    mma16816(acc[mt][nt], al, ph);
                }
            }
        }
        __syncthreads();
    }

    // ---- epilogue ----
    #pragma unroll
    for (int mt = 0; mt < 4; mt++) {
        int rl = warp_m * 64 + mt * 16 + (lane >> 2);   // local tile row (0..127)
        int rh = rl + 8;
        if (MODE == 0) {
            int v1 = sTgt[rl], v2 = sTgt[rh];
            #pragma unroll
            for (int nt = 0; nt < 4; nt++) {
                int c = col0 + warp_n * 32 + nt * 8 + 2 * (lane & 3);
                if (v1 >= 0) {
                    atomicAdd(&Out[(size_t)v1 * dout + c],     acc[mt][nt][0]);
                    atomicAdd(&Out[(size_t)v1 * dout + c + 1], acc[mt][nt][1]);
                }
                if (v2 >= 0) {
                    atomicAdd(&Out[(size_t)v2 * dout + c],     acc[mt][nt][2]);
                    atomicAdd(&Out[(size_t)v2 * dout + c + 1], acc[mt][nt][3]);
                }
            }
        } else {
            int g1 = row0 + rl, g2 = row0 + rh;
            #pragma unroll
            for (int nt = 0; nt < 4; nt++) {
                int c = col0 + warp_n * 32 + nt * 8 + 2 * (lane & 3);
                float b0 = bias[c], b1 = bias[c + 1];
                if (g1 < Nrows) {
                    Out[(size_t)g1 * dout + c]     = tanhf(acc[mt][nt][0] + b0);
                    Out[(size_t)g1 * dout + c + 1] = tanhf(acc[mt][nt][1] + b1);
                }
                if (g2 < Nrows) {
                    Out[(size_t)g2 * dout + c]     = tanhf(acc[mt][nt][2] + b0);
                    Out[(size_t)g2 * dout + c + 1] = tanhf(acc[mt][nt][3] + b1);
                }
            }
        }
    }
}

// ---------------- host-side driver ----------------
static void run_gnn_layer(const float* Sin, int din, int N, int E,
                          const __nv_bfloat16* Weh, const __nv_bfloat16* Wel,
                          const float* ls, const float* lb,
                          const __nv_bfloat16* Wdh, const __nv_bfloat16* Wdl,
                          const float* bias, float* dest, float* Mbuf,
                          const int* src, const int* tgt) {
    long long n4 = (long long)N * din / 4;
    clear_f4_kernel<<<4096, 256>>>((float4*)Mbuf, n4);
    dim3 egrid((E + 127) / 128, 4, din / 128);
    mma_gemm<0><<<egrid, 256, SMEM_BYTES>>>(Sin, din, 2 * din, Weh, Wel, din, Mbuf,
                                            src, tgt, nullptr, 0);
    gelu_ln_kernel<<<(N + 7) / 8, 256>>>(Mbuf, ls, lb, din, N);
    dim3 dgrid((N + 127) / 128, 1, 2);
    mma_gemm<1><<<dgrid, 256, SMEM_BYTES>>>(Mbuf, din, din, Wdh, Wdl, 256, dest,
                                            nullptr, nullptr, bias, N);
}

extern "C" void kernel_launch(void* const* d_in, const int* in_sizes, int n_in,
                              void* d_out, int out_size) {
    const int*   ids   = (const int*)d_in[0];
    const int*   te    = (const int*)d_in[1];
    const float* embed = (const float*)d_in[2];
    const float* WeI   = (const float*)d_in[3];
    const float* lsI   = (const float*)d_in[4];
    const float* lbI   = (const float*)d_in[5];
    const float* WdI   = (const float*)d_in[6];
    const float* bdI   = (const float*)d_in[7];
    const float* WeO   = (const float*)d_in[8];
    const float* lsO   = (const float*)d_in[9];
    const float* lbO   = (const float*)d_in[10];
    const float* WdO   = (const float*)d_in[11];
    const float* bdO   = (const float*)d_in[12];
    float* out = (float*)d_out;

    int N = in_sizes[0];
    int E = in_sizes[1] / 3;
    const int* etype = te;
    const int* src   = te + E;
    const int* tgt   = te + 2 * E;

    float *S0, *S1, *M, *SAVE;
    __nv_bfloat16 *WeIh, *WeIl, *WeOh, *WeOl, *WdIh, *WdIl, *WdOh, *WdOl;
    cudaGetSymbolAddress((void**)&S0, g_S0);
    cudaGetSymbolAddress((void**)&S1, g_S1);
    cudaGetSymbolAddress((void**)&M,  g_M);
    cudaGetSymbolAddress((void**)&SAVE, g_SAVE);
    cudaGetSymbolAddress((void**)&WeIh, g_WeI_h);
    cudaGetSymbolAddress((void**)&WeIl, g_WeI_l);
    cudaGetSymbolAddress((void**)&WeOh, g_WeO_h);
    cudaGetSymbolAddress((void**)&WeOl, g_WeO_l);
    cudaGetSymbolAddress((void**)&WdIh, g_WdI_h);
    cudaGetSymbolAddress((void**)&WdIl, g_WdI_l);
    cudaGetSymbolAddress((void**)&WdOh, g_WdO_h);
    cudaGetSymbolAddress((void**)&WdOl, g_WdO_l);

    cudaFuncSetAttribute(mma_gemm<0>, cudaFuncAttributeMaxDynamicSharedMemorySize, SMEM_BYTES);
    cudaFuncSetAttribute(mma_gemm<1>, cudaFuncAttributeMaxDynamicSharedMemorySize, SMEM_BYTES);

    // --- preprocessing ---
    clear_counts_kernel<<<1, 32>>>();
    count_types_kernel<<<(E + 255) / 256, 256>>>(etype, E);
    offsets_kernel<<<1, 1>>>();
    scatter_types_kernel<<<(E + 255) / 256, 256>>>(etype, E);

    int nWeI = 6 * 4 * 256 * 512, nWeO = 2 * 4 * 512 * 1024;
    int nWdI = 6 * 256 * 256,     nWdO = 2 * 256 * 512;
    conv_bf16_kernel<<<(nWeI + 255) / 256, 256>>>(WeI, WeIh, WeIl, nWeI);
    conv_bf16_kernel<<<(nWeO + 255) / 256, 256>>>(WeO, WeOh, WeOl, nWeO);
    conv_bf16_kernel<<<(nWdI + 255) / 256, 256>>>(WdI, WdIh, WdIl, nWdI);
    conv_bf16_kernel<<<(nWdO + 255) / 256, 256>>>(WdO, WdOh, WdOl, nWdO);

    embed_kernel<<<(N * 64 + 255) / 256, 256>>>((const float4*)embed, ids, (float4*)S0, N);

    float* S = S0;
    float* Snext = S1;

    for (int b = 0; b < 2; b++) {
        copy256_kernel<<<(N * 64 + 255) / 256, 256>>>((const float4*)S, (float4*)SAVE, N);
        for (int i = 0; i < 3; i++) {
            int l = 3 * b + i;
            run_gnn_layer(S, 256, N, E,
                          WeIh + (size_t)l * 4 * 256 * 512, WeIl + (size_t)l * 4 * 256 * 512,
                          lsI + (size_t)l * 256, lbI + (size_t)l * 256,
                          WdIh + (size_t)l * 256 * 256, WdIl + (size_t)l * 256 * 256,
                          bdI + (size_t)l * 256,
                          Snext, M, src, tgt);
            float* tmp = S; S = Snext; Snext = tmp;
        }
        concat_kernel<<<(N * 128 + 255) / 256, 256>>>((const float4*)SAVE, (const float4*)S,
                                                      (float4*)Snext, N);
        { float* tmp = S; S = Snext; Snext = tmp; }
        float* dest = (b == 1) ? out : Snext;
        run_gnn_layer(S, 512, N, E,
                      WeOh + (size_t)b * 4 * 512 * 1024, WeOl + (size_t)b * 4 * 512 * 1024,
                      lsO + (size_t)b * 512, lbO + (size_t)b * 512,
                      WdOh + (size_t)b * 256 * 512, WdOl + (size_t)b * 256 * 512,
                      bdO + (size_t)b * 256,
                      dest, M, src, tgt);
        if (b == 0) { float* tmp = S; S = Snext; Snext = tmp; }
    }
}

// round 4
// speedup vs baseline: 2.4753x; 1.3266x over previous
#include <cuda_runtime.h>
#include <cuda_bf16.h>
#include <math.h>
#include <stdint.h>

#define MAXN 100000
#define MAXE 320000

// ---------------- scratch (device globals; no allocs allowed) ----------------
__device__ __align__(16) float g_S0[(size_t)MAXN * 512];
__device__ __align__(16) float g_S1[(size_t)MAXN * 512];
__device__ __align__(16) float g_M [(size_t)MAXN * 512];
__device__ __align__(16) float g_SAVE[(size_t)MAXN * 256];

// bf16 hi/lo state + message splits
__device__ __align__(16) __nv_bfloat16 g_Sh[(size_t)MAXN * 512], g_Sl[(size_t)MAXN * 512];
__device__ __align__(16) __nv_bfloat16 g_Mh[(size_t)MAXN * 512], g_Ml[(size_t)MAXN * 512];

// bf16 hi/lo weight splits (natural [dout][K] layout == col-major B for mma.row.col)
__device__ __align__(16) __nv_bfloat16 g_WeI_h[6 * 4 * 256 * 512],  g_WeI_l[6 * 4 * 256 * 512];
__device__ __align__(16) __nv_bfloat16 g_WeO_h[2 * 4 * 512 * 1024], g_WeO_l[2 * 4 * 512 * 1024];
__device__ __align__(16) __nv_bfloat16 g_WdI_h[6 * 256 * 256],      g_WdI_l[6 * 256 * 256];
__device__ __align__(16) __nv_bfloat16 g_WdO_h[2 * 256 * 512],      g_WdO_l[2 * 256 * 512];

__device__ int g_typeEdges[MAXE];
__device__ int g_cnt[4], g_off[4], g_cur[4];

// ---------------- helpers ----------------
__device__ __forceinline__ uint32_t smem_u32(const void* p) {
    uint32_t a;
    asm("{ .reg .u64 t; cvta.to.shared.u64 t, %1; cvt.u32.u64 %0, t; }" : "=r"(a) : "l"(p));
    return a;
}

__device__ __forceinline__ void ldm_x4(uint32_t addr, uint32_t r[4]) {
    asm volatile("ldmatrix.sync.aligned.m8n8.x4.shared.b16 {%0,%1,%2,%3}, [%4];"
                 : "=r"(r[0]), "=r"(r[1]), "=r"(r[2]), "=r"(r[3]) : "r"(addr));
}

__device__ __forceinline__ void mma16816(float c[4], const uint32_t a[4], const uint32_t b[2]) {
    asm volatile(
        "mma.sync.aligned.m16n8k16.row.col.f32.bf16.bf16.f32 "
        "{%0,%1,%2,%3}, {%4,%5,%6,%7}, {%8,%9}, {%0,%1,%2,%3};"
        : "+f"(c[0]), "+f"(c[1]), "+f"(c[2]), "+f"(c[3])
        : "r"(a[0]), "r"(a[1]), "r"(a[2]), "r"(a[3]), "r"(b[0]), "r"(b[1]));
}

__device__ __forceinline__ void cpa16(uint32_t dst, const void* src) {
    asm volatile("cp.async.cg.shared.global [%0], [%1], 16;" :: "r"(dst), "l"(src) : "memory");
}

__device__ __forceinline__ uint32_t pk_hi(float a, float b) {
    __nv_bfloat162 t = __floats2bfloat162_rn(a, b);
    return reinterpret_cast<uint32_t&>(t);
}
__device__ __forceinline__ float bf_rt(float a) {
    return __bfloat162float(__float2bfloat16(a));
}

// ---------------- small utility kernels ----------------
__global__ void clear_f4_kernel(float4* p, long long n4) {
    long long i = (long long)blockIdx.x * blockDim.x + threadIdx.x;
    long long stride = (long long)gridDim.x * blockDim.x;
    float4 z = make_float4(0.f, 0.f, 0.f, 0.f);
    for (; i < n4; i += stride) p[i] = z;
}

__global__ void clear_counts_kernel() {
    int i = threadIdx.x;
    if (i < 4) { g_cnt[i] = 0; g_cur[i] = 0; }
}

__global__ void count_types_kernel(const int* __restrict__ etype, int E) {
    int e = blockIdx.x * blockDim.x + threadIdx.x;
    if (e < E) atomicAdd(&g_cnt[etype[e] - 1], 1);
}

__global__ void offsets_kernel() {
    if (threadIdx.x == 0) {
        g_off[0] = 0;
        g_off[1] = g_cnt[0];
        g_off[2] = g_cnt[0] + g_cnt[1];
        g_off[3] = g_cnt[0] + g_cnt[1] + g_cnt[2];
    }
}

__global__ void scatter_types_kernel(const int* __restrict__ etype, int E) {
    int e = blockIdx.x * blockDim.x + threadIdx.x;
    if (e < E) {
        int t = etype[e] - 1;
        int p = atomicAdd(&g_cur[t], 1);
        g_typeEdges[g_off[t] + p] = e;
    }
}

__global__ void conv_bf16_kernel(const float* __restrict__ w, __nv_bfloat16* __restrict__ hi,
                                 __nv_bfloat16* __restrict__ lo, int n) {
    int i = blockIdx.x * blockDim.x + threadIdx.x;
    if (i >= n) return;
    float x = w[i];
    __nv_bfloat16 h = __float2bfloat16(x);
    hi[i] = h;
    lo[i] = __float2bfloat16(x - __bfloat162float(h));
}

// split fp32 state -> bf16 hi/lo (vectorized: 4 floats per thread)
__global__ void split_kernel(const float4* __restrict__ S, uint2* __restrict__ Sh,
                             uint2* __restrict__ Sl, long long n4) {
    long long i = (long long)blockIdx.x * blockDim.x + threadIdx.x;
    if (i >= n4) return;
    float4 v = S[i];
    uint32_t h0 = pk_hi(v.x, v.y), h1 = pk_hi(v.z, v.w);
    uint32_t l0 = pk_hi(v.x - bf_rt(v.x), v.y - bf_rt(v.y));
    uint32_t l1 = pk_hi(v.z - bf_rt(v.z), v.w - bf_rt(v.w));
    Sh[i] = make_uint2(h0, h1);
    Sl[i] = make_uint2(l0, l1);
}

__global__ void embed_kernel(const float4* __restrict__ tab, const int* __restrict__ ids,
                             float4* __restrict__ outS, int N) {
    int idx = blockIdx.x * blockDim.x + threadIdx.x;
    if (idx >= N * 64) return;
    int node = idx >> 6, c = idx & 63;
    int r = ids[node];
    outS[(size_t)node * 64 + c] = tab[(size_t)r * 64 + c];
}

__global__ void copy256_kernel(const float4* __restrict__ src, float4* __restrict__ dst, int N) {
    int idx = blockIdx.x * blockDim.x + threadIdx.x;
    if (idx < N * 64) dst[idx] = src[idx];
}

__global__ void concat_kernel(const float4* __restrict__ save, const float4* __restrict__ x,
                              float4* __restrict__ res, int N) {
    int idx = blockIdx.x * blockDim.x + threadIdx.x;
    if (idx >= N * 128) return;
    int node = idx >> 7, c = idx & 127;
    float4 v = (c < 64) ? save[(size_t)node * 64 + c] : x[(size_t)node * 64 + (c - 64)];
    res[(size_t)node * 128 + c] = v;
}

// gelu + layernorm; emits bf16 hi/lo directly (no fp32 output needed downstream)
__global__ void gelu_ln_kernel(const float* __restrict__ M, const float* __restrict__ s,
                               const float* __restrict__ b,
                               __nv_bfloat16* __restrict__ Mh, __nv_bfloat16* __restrict__ Ml,
                               int dm, int N) {
    int warp = (blockIdx.x * blockDim.x + threadIdx.x) >> 5;
    int lane = threadIdx.x & 31;
    if (warp >= N) return;
    const float* row = M + (size_t)warp * dm;
    int per = dm >> 5;
    float v[16];
    float sum = 0.f;
    for (int i = 0; i < per; i++) {
        float x = row[i * 32 + lane];
        float g = 0.5f * x * (1.0f + erff(x * 0.70710678118654752f));
        v[i] = g; sum += g;
    }
    #pragma unroll
    for (int o = 16; o > 0; o >>= 1) sum += __shfl_xor_sync(0xFFFFFFFF, sum, o);
    float mu = sum / (float)dm;
    float vs = 0.f;
    for (int i = 0; i < per; i++) { float d = v[i] - mu; vs += d * d; }
    #pragma unroll
    for (int o = 16; o > 0; o >>= 1) vs += __shfl_xor_sync(0xFFFFFFFF, vs, o);
    float inv = rsqrtf(vs / (float)dm + 1e-5f);
    for (int i = 0; i < per; i++) {
        int c = i * 32 + lane;
        float y = (v[i] - mu) * inv * s[c] + b[c];
        __nv_bfloat16 h = __float2bfloat16(y);
        Mh[(size_t)warp * dm + c] = h;
        Ml[(size_t)warp * dm + c] = __float2bfloat16(y - __bfloat162float(h));
    }
}

// ---------------- mma.sync GEMM (MODE 0: edge gather+scatter, MODE 1: dense+tanh) ----------------
// CTA tile 128(M) x 256(N), K chunk 32 bf16, bf16x3 split (hh + hl + lh).
// 512 threads = 16 warps (2x8), warp tile 64x32.
// SMEM stage 60KB: A_hi[128][40] A_lo | B_hi[256][40] B_lo (80B padded rows). Double buffered.

#define ROWB 80
#define ASPL 10240          // A lo offset (128*80)
#define BOFF 20480          // B hi offset
#define BSPL 20480          // B lo relative offset (256*80)
#define STAGE 61440
#define SMEM_BYTES (1024 + 2 * STAGE)

template<int MODE>
__global__ __launch_bounds__(512, 1)
void mma_gemm(const __nv_bfloat16* __restrict__ Ah, const __nv_bfloat16* __restrict__ Al,
              int strideA, int K,
              const __nv_bfloat16* __restrict__ Bh_, const __nv_bfloat16* __restrict__ Bl_,
              int dout, float* __restrict__ Out,
              const int* __restrict__ src, const int* __restrict__ tgt,
              const float* __restrict__ bias, int Nrows) {
    extern __shared__ char smem[];
    int tid = threadIdx.x;
    int wid = tid >> 5, lane = tid & 31;
    int row0 = blockIdx.x * 128;
    int col0 = blockIdx.z * 256;

    const __nv_bfloat16 *Bh, *Bl;
    int cnt = 0, offT = 0;
    if (MODE == 0) {
        int t = blockIdx.y;
        cnt = g_cnt[t];
        if (row0 >= cnt) return;
        offT = g_off[t];
        Bh = Bh_ + (size_t)t * dout * K;
        Bl = Bl_ + (size_t)t * dout * K;
    } else {
        if (row0 >= Nrows) return;
        Bh = Bh_; Bl = Bl_;
    }

    int* sSrc = (int*)smem;
    int* sTgt = (int*)(smem + 512);
    char* tiles = smem + 1024;
    uint32_t sb = smem_u32(tiles);

    if (MODE == 0 && tid < 128) {
        int r = row0 + tid;
        int sn = 0, tn = -1;
        if (r < cnt) { int e = g_typeEdges[offT + r]; sn = src[e]; tn = tgt[e]; }
        sSrc[tid] = sn; sTgt[tid] = tn;
    }
    __syncthreads();

    // ---- ldmatrix base addresses ----
    int warp_m = wid >> 3, warp_n = wid & 7;
    uint32_t aAddr[4], bAddr[2];
    {
        int r = (lane & 15), hi8 = (lane >> 4) & 1;
        #pragma unroll
        for (int mt = 0; mt < 4; mt++)
            aAddr[mt] = sb + (warp_m * 64 + mt * 16 + r) * ROWB + hi8 * 16;
        int nr = hi8 * 8 + (lane & 7), kq = (lane >> 3) & 1;
        #pragma unroll
        for (int g = 0; g < 2; g++)
            bAddr[g] = sb + BOFF + (warp_n * 32 + g * 16 + nr) * ROWB + kq * 16;
    }

    float acc[4][4][4];
    #pragma unroll
    for (int i = 0; i < 4; i++)
        #pragma unroll
        for (int j = 0; j < 4; j++)
            #pragma unroll
            for (int q = 0; q < 4; q++) acc[i][j][q] = 0.f;

    const int nch = K >> 5;

    // ---- async chunk loader: pure byte movement (state pre-split to bf16) ----
    auto load_chunk = [&](int c) {
        int kt = c * 32;
        uint32_t stg = sb + (c & 1) * STAGE;
        bool useSrc = true; int colb = kt;
        if (MODE == 0) { useSrc = kt < strideA; colb = useSrc ? kt : kt - strideA; }
        // A: 128 rows x (hi 64B + lo 64B) = 1024 x 16B
        #pragma unroll
        for (int i = 0; i < 2; i++) {
            int slot = tid + i * 512;
            int m = slot >> 3, u3 = slot & 7;
            int split = u3 >> 2, u = u3 & 3;
            const __nv_bfloat16* base = split ? Al : Ah;
            const __nv_bfloat16* srcp;
            if (MODE == 0) {
                int node = useSrc ? sSrc[m] : sTgt[m];
                if (node < 0) node = 0;
                srcp = base + (size_t)node * strideA + colb + u * 8;
            } else {
                int r = row0 + m; if (r >= Nrows) r = 0;
                srcp = base + (size_t)r * strideA + kt + u * 8;
            }
            cpa16(stg + split * ASPL + m * ROWB + u * 16, srcp);
        }
        // B: 256 rows x (hi 64B + lo 64B) = 2048 x 16B
        #pragma unroll
        for (int i = 0; i < 4; i++) {
            int slot = tid + i * 512;
            int n = slot >> 3, u3 = slot & 7;
            int split = u3 >> 2, u = u3 & 3;
            const __nv_bfloat16* bs = split ? Bl : Bh;
            cpa16(stg + BOFF + split * BSPL + n * ROWB + u * 16,
                  bs + (size_t)(col0 + n) * K + kt + u * 8);
        }
        asm volatile("cp.async.commit_group;" ::: "memory");
    };

    load_chunk(0);

    for (int c = 0; c < nch; c++) {
        if (c + 1 < nch) {
            load_chunk(c + 1);
            asm volatile("cp.async.wait_group 1;" ::: "memory");
        } else {
            asm volatile("cp.async.wait_group 0;" ::: "memory");
        }
        __syncthreads();
        uint32_t stoff = (c & 1) * STAGE;
        #pragma unroll
        for (int ks = 0; ks < 2; ks++) {
            uint32_t ko = stoff + ks * 32;
            uint32_t bhf[2][4], blf[2][4];
            ldm_x4(bAddr[0] + ko, bhf[0]);
            ldm_x4(bAddr[1] + ko, bhf[1]);
            ldm_x4(bAddr[0] + ko + BSPL, blf[0]);
            ldm_x4(bAddr[1] + ko + BSPL, blf[1]);
            #pragma unroll
            for (int mt = 0; mt < 4; mt++) {
                uint32_t ah[4], al[4];
                ldm_x4(aAddr[mt] + ko, ah);
                ldm_x4(aAddr[mt] + ko + ASPL, al);
                #pragma unroll
                for (int nt = 0; nt < 4; nt++) {
                    const uint32_t* ph = &bhf[nt >> 1][(nt & 1) * 2];
                    const uint32_t* pl = &blf[nt >> 1][(nt & 1) * 2];
                    mma16816(acc[mt][nt], ah, ph);
                    mma16816(acc[mt][nt], ah, pl);
                    mma16816(acc[mt][nt], al, ph);
                }
            }
        }
        __syncthreads();
    }

    // ---- epilogue ----
    #pragma unroll
    for (int mt = 0; mt < 4; mt++) {
        int rl = warp_m * 64 + mt * 16 + (lane >> 2);
        int rh = rl + 8;
        if (MODE == 0) {
            int v1 = sTgt[rl], v2 = sTgt[rh];
            #pragma unroll
            for (int nt = 0; nt < 4; nt++) {
                int c = col0 + warp_n * 32 + nt * 8 + 2 * (lane & 3);
                if (v1 >= 0) {
                    atomicAdd(&Out[(size_t)v1 * dout + c],     acc[mt][nt][0]);
                    atomicAdd(&Out[(size_t)v1 * dout + c + 1], acc[mt][nt][1]);
                }
                if (v2 >= 0) {
                    atomicAdd(&Out[(size_t)v2 * dout + c],     acc[mt][nt][2]);
                    atomicAdd(&Out[(size_t)v2 * dout + c + 1], acc[mt][nt][3]);
                }
            }
        } else {
            int g1 = row0 + rl, g2 = row0 + rh;
            #pragma unroll
            for (int nt = 0; nt < 4; nt++) {
                int c = col0 + warp_n * 32 + nt * 8 + 2 * (lane & 3);
                float b0 = bias[c], b1 = bias[c + 1];
                if (g1 < Nrows) {
                    Out[(size_t)g1 * dout + c]     = tanhf(acc[mt][nt][0] + b0);
                    Out[(size_t)g1 * dout + c + 1] = tanhf(acc[mt][nt][1] + b1);
                }
                if (g2 < Nrows) {
                    Out[(size_t)g2 * dout + c]     = tanhf(acc[mt][nt][2] + b0);
                    Out[(size_t)g2 * dout + c + 1] = tanhf(acc[mt][nt][3] + b1);
                }
            }
        }
    }
}

// ---------------- host-side driver ----------------
static void run_gnn_layer(const float* Sin, int din, int N, int E,
                          __nv_bfloat16* Sh, __nv_bfloat16* Sl,
                          __nv_bfloat16* Mh, __nv_bfloat16* Ml,
                          const __nv_bfloat16* Weh, const __nv_bfloat16* Wel,
                          const float* ls, const float* lb,
                          const __nv_bfloat16* Wdh, const __nv_bfloat16* Wdl,
                          const float* bias, float* dest, float* Mbuf,
                          const int* src, const int* tgt) {
    long long n4 = (long long)N * din / 4;
    clear_f4_kernel<<<4096, 256>>>((float4*)Mbuf, n4);
    split_kernel<<<(unsigned)((n4 + 255) / 256), 256>>>((const float4*)Sin, (uint2*)Sh,
                                                        (uint2*)Sl, n4);
    // edge GEMM: K=2*din, dout=din; N-tile 256
    dim3 egrid((E + 127) / 128, 4, din / 256 ? din / 256 : 1);
    mma_gemm<0><<<egrid, 512, SMEM_BYTES>>>(Sh, Sl, din, 2 * din, Weh, Wel, din, Mbuf,
                                            src, tgt, nullptr, 0);
    gelu_ln_kernel<<<(N + 7) / 8, 256>>>(Mbuf, ls, lb, Mh, Ml, din, N);
    // dense: K=din, dout=256, single col tile
    dim3 dgrid((N + 127) / 128, 1, 1);
    mma_gemm<1><<<dgrid, 512, SMEM_BYTES>>>(Mh, Ml, din, din, Wdh, Wdl, 256, dest,
                                            nullptr, nullptr, bias, N);
}

extern "C" void kernel_launch(void* const* d_in, const int* in_sizes, int n_in,
                              void* d_out, int out_size) {
    const int*   ids   = (const int*)d_in[0];
    const int*   te    = (const int*)d_in[1];
    const float* embed = (const float*)d_in[2];
    const float* WeI   = (const float*)d_in[3];
    const float* lsI   = (const float*)d_in[4];
    const float* lbI   = (const float*)d_in[5];
    const float* WdI   = (const float*)d_in[6];
    const float* bdI   = (const float*)d_in[7];
    const float* WeO   = (const float*)d_in[8];
    const float* lsO   = (const float*)d_in[9];
    const float* lbO   = (const float*)d_in[10];
    const float* WdO   = (const float*)d_in[11];
    const float* bdO   = (const float*)d_in[12];
    float* out = (float*)d_out;

    int N = in_sizes[0];
    int E = in_sizes[1] / 3;
    const int* etype = te;
    const int* src   = te + E;
    const int* tgt   = te + 2 * E;

    float *S0, *S1, *M, *SAVE;
    __nv_bfloat16 *Sh, *Sl, *Mh, *Ml;
    __nv_bfloat16 *WeIh, *WeIl, *WeOh, *WeOl, *WdIh, *WdIl, *WdOh, *WdOl;
    cudaGetSymbolAddress((void**)&S0, g_S0);
    cudaGetSymbolAddress((void**)&S1, g_S1);
    cudaGetSymbolAddress((void**)&M,  g_M);
    cudaGetSymbolAddress((void**)&SAVE, g_SAVE);
    cudaGetSymbolAddress((void**)&Sh, g_Sh);
    cudaGetSymbolAddress((void**)&Sl, g_Sl);
    cudaGetSymbolAddress((void**)&Mh, g_Mh);
    cudaGetSymbolAddress((void**)&Ml, g_Ml);
    cudaGetSymbolAddress((void**)&WeIh, g_WeI_h);
    cudaGetSymbolAddress((void**)&WeIl, g_WeI_l);
    cudaGetSymbolAddress((void**)&WeOh, g_WeO_h);
    cudaGetSymbolAddress((void**)&WeOl, g_WeO_l);
    cudaGetSymbolAddress((void**)&WdIh, g_WdI_h);
    cudaGetSymbolAddress((void**)&WdIl, g_WdI_l);
    cudaGetSymbolAddress((void**)&WdOh, g_WdO_h);
    cudaGetSymbolAddress((void**)&WdOl, g_WdO_l);

    cudaFuncSetAttribute(mma_gemm<0>, cudaFuncAttributeMaxDynamicSharedMemorySize, SMEM_BYTES);
    cudaFuncSetAttribute(mma_gemm<1>, cudaFuncAttributeMaxDynamicSharedMemorySize, SMEM_BYTES);

    // --- preprocessing ---
    clear_counts_kernel<<<1, 32>>>();
    count_types_kernel<<<(E + 255) / 256, 256>>>(etype, E);
    offsets_kernel<<<1, 1>>>();
    scatter_types_kernel<<<(E + 255) / 256, 256>>>(etype, E);

    int nWeI = 6 * 4 * 256 * 512, nWeO = 2 * 4 * 512 * 1024;
    int nWdI = 6 * 256 * 256,     nWdO = 2 * 256 * 512;
    conv_bf16_kernel<<<(nWeI + 255) / 256, 256>>>(WeI, WeIh, WeIl, nWeI);
    conv_bf16_kernel<<<(nWeO + 255) / 256, 256>>>(WeO, WeOh, WeOl, nWeO);
    conv_bf16_kernel<<<(nWdI + 255) / 256, 256>>>(WdI, WdIh, WdIl, nWdI);
    conv_bf16_kernel<<<(nWdO + 255) / 256, 256>>>(WdO, WdOh, WdOl, nWdO);

    embed_kernel<<<(N * 64 + 255) / 256, 256>>>((const float4*)embed, ids, (float4*)S0, N);

    float* S = S0;
    float* Snext = S1;

    for (int b = 0; b < 2; b++) {
        copy256_kernel<<<(N * 64 + 255) / 256, 256>>>((const float4*)S, (float4*)SAVE, N);
        for (int i = 0; i < 3; i++) {
            int l = 3 * b + i;
            run_gnn_layer(S, 256, N, E, Sh, Sl, Mh, Ml,
                          WeIh + (size_t)l * 4 * 256 * 512, WeIl + (size_t)l * 4 * 256 * 512,
                          lsI + (size_t)l * 256, lbI + (size_t)l * 256,
                          WdIh + (size_t)l * 256 * 256, WdIl + (size_t)l * 256 * 256,
                          bdI + (size_t)l * 256,
                          Snext, M, src, tgt);
            float* tmp = S; S = Snext; Snext = tmp;
        }
        concat_kernel<<<(N * 128 + 255) / 256, 256>>>((const float4*)SAVE, (const float4*)S,
                                                      (float4*)Snext, N);
        { float* tmp = S; S = Snext; Snext = tmp; }
        float* dest = (b == 1) ? out : Snext;
        run_gnn_layer(S, 512, N, E, Sh, Sl, Mh, Ml,
                      WeOh + (size_t)b * 4 * 512 * 1024, WeOl + (size_t)b * 4 * 512 * 1024,
                      lsO + (size_t)b * 512, lbO + (size_t)b * 512,
                      WdOh + (size_t)b * 256 * 512, WdOl + (size_t)b * 256 * 512,
                      bdO + (size_t)b * 256,
                      dest, M, src, tgt);
        if (b == 0) { float* tmp = S; S = Snext; Snext = tmp; }
    }
}

// round 5
// speedup vs baseline: 2.4961x; 1.0084x over previous
#include <cuda_runtime.h>
#include <cuda_bf16.h>
#include <math.h>
#include <stdint.h>

#define MAXN 100000
#define MAXE 320000

// ---------------- scratch (device globals; no allocs allowed) ----------------
__device__ __align__(16) float g_S0[(size_t)MAXN * 256];
__device__ __align__(16) float g_S1[(size_t)MAXN * 256];
__device__ __align__(16) float g_M [(size_t)MAXN * 512];
__device__ __align__(16) float g_SAVE[(size_t)MAXN * 256];

// bf16 hi/lo state + message splits
__device__ __align__(16) __nv_bfloat16 g_Sh[(size_t)MAXN * 512], g_Sl[(size_t)MAXN * 512];
__device__ __align__(16) __nv_bfloat16 g_Mh[(size_t)MAXN * 512], g_Ml[(size_t)MAXN * 512];

// bf16 hi/lo weight splits (natural [dout][K] layout == col-major B for mma.row.col)
__device__ __align__(16) __nv_bfloat16 g_WeI_h[6 * 4 * 256 * 512],  g_WeI_l[6 * 4 * 256 * 512];
__device__ __align__(16) __nv_bfloat16 g_WeO_h[2 * 4 * 512 * 1024], g_WeO_l[2 * 4 * 512 * 1024];
__device__ __align__(16) __nv_bfloat16 g_WdI_h[6 * 256 * 256],      g_WdI_l[6 * 256 * 256];
__device__ __align__(16) __nv_bfloat16 g_WdO_h[2 * 256 * 512],      g_WdO_l[2 * 256 * 512];

__device__ int g_typeEdges[MAXE];
__device__ int g_cnt[4], g_off[4], g_cur[4];

// ---------------- helpers ----------------
__device__ __forceinline__ uint32_t smem_u32(const void* p) {
    uint32_t a;
    asm("{ .reg .u64 t; cvta.to.shared.u64 t, %1; cvt.u32.u64 %0, t; }" : "=r"(a) : "l"(p));
    return a;
}

__device__ __forceinline__ void ldm_x4(uint32_t addr, uint32_t r[4]) {
    asm volatile("ldmatrix.sync.aligned.m8n8.x4.shared.b16 {%0,%1,%2,%3}, [%4];"
                 : "=r"(r[0]), "=r"(r[1]), "=r"(r[2]), "=r"(r[3]) : "r"(addr));
}

__device__ __forceinline__ void mma16816(float c[4], const uint32_t a[4], const uint32_t b[2]) {
    asm volatile(
        "mma.sync.aligned.m16n8k16.row.col.f32.bf16.bf16.f32 "
        "{%0,%1,%2,%3}, {%4,%5,%6,%7}, {%8,%9}, {%0,%1,%2,%3};"
        : "+f"(c[0]), "+f"(c[1]), "+f"(c[2]), "+f"(c[3])
        : "r"(a[0]), "r"(a[1]), "r"(a[2]), "r"(a[3]), "r"(b[0]), "r"(b[1]));
}

__device__ __forceinline__ void cpa16(uint32_t dst, const void* src) {
    asm volatile("cp.async.cg.shared.global [%0], [%1], 16;" :: "r"(dst), "l"(src) : "memory");
}

// vectorized f32 reduction (PTX ISA 8.1, sm_90+)
__device__ __forceinline__ void red2(float* addr, float a, float b) {
    asm volatile("red.global.add.v2.f32 [%0], {%1, %2};" :: "l"(addr), "f"(a), "f"(b) : "memory");
}

__device__ __forceinline__ uint32_t pk_hi(float a, float b) {
    __nv_bfloat162 t = __floats2bfloat162_rn(a, b);
    return reinterpret_cast<uint32_t&>(t);
}
__device__ __forceinline__ float bf_rt(float a) {
    return __bfloat162float(__float2bfloat16(a));
}

// ---------------- small utility kernels ----------------
__global__ void clear_f4_kernel(float4* p, long long n4) {
    long long i = (long long)blockIdx.x * blockDim.x + threadIdx.x;
    long long stride = (long long)gridDim.x * blockDim.x;
    float4 z = make_float4(0.f, 0.f, 0.f, 0.f);
    for (; i < n4; i += stride) p[i] = z;
}

__global__ void clear_counts_kernel() {
    int i = threadIdx.x;
    if (i < 4) { g_cnt[i] = 0; g_cur[i] = 0; }
}

__global__ void count_types_kernel(const int* __restrict__ etype, int E) {
    int e = blockIdx.x * blockDim.x + threadIdx.x;
    if (e < E) atomicAdd(&g_cnt[etype[e] - 1], 1);
}

__global__ void offsets_kernel() {
    if (threadIdx.x == 0) {
        g_off[0] = 0;
        g_off[1] = g_cnt[0];
        g_off[2] = g_cnt[0] + g_cnt[1];
        g_off[3] = g_cnt[0] + g_cnt[1] + g_cnt[2];
    }
}

__global__ void scatter_types_kernel(const int* __restrict__ etype, int E) {
    int e = blockIdx.x * blockDim.x + threadIdx.x;
    if (e < E) {
        int t = etype[e] - 1;
        int p = atomicAdd(&g_cur[t], 1);
        g_typeEdges[g_off[t] + p] = e;
    }
}

__global__ void conv_bf16_kernel(const float* __restrict__ w, __nv_bfloat16* __restrict__ hi,
                                 __nv_bfloat16* __restrict__ lo, int n) {
    int i = blockIdx.x * blockDim.x + threadIdx.x;
    if (i >= n) return;
    float x = w[i];
    __nv_bfloat16 h = __float2bfloat16(x);
    hi[i] = h;
    lo[i] = __float2bfloat16(x - __bfloat162float(h));
}

// split fp32 state -> bf16 hi/lo (used once, after embed)
__global__ void split_kernel(const float4* __restrict__ S, uint2* __restrict__ Sh,
                             uint2* __restrict__ Sl, long long n4) {
    long long i = (long long)blockIdx.x * blockDim.x + threadIdx.x;
    if (i >= n4) return;
    float4 v = S[i];
    uint32_t h0 = pk_hi(v.x, v.y), h1 = pk_hi(v.z, v.w);
    uint32_t l0 = pk_hi(v.x - bf_rt(v.x), v.y - bf_rt(v.y));
    uint32_t l1 = pk_hi(v.z - bf_rt(v.z), v.w - bf_rt(v.w));
    Sh[i] = make_uint2(h0, h1);
    Sl[i] = make_uint2(l0, l1);
}

__global__ void embed_kernel(const float4* __restrict__ tab, const int* __restrict__ ids,
                             float4* __restrict__ outS, int N) {
    int idx = blockIdx.x * blockDim.x + threadIdx.x;
    if (idx >= N * 64) return;
    int node = idx >> 6, c = idx & 63;
    int r = ids[node];
    outS[(size_t)node * 64 + c] = tab[(size_t)r * 64 + c];
}

__global__ void copy256_kernel(const float4* __restrict__ src, float4* __restrict__ dst, int N) {
    int idx = blockIdx.x * blockDim.x + threadIdx.x;
    if (idx < N * 64) dst[idx] = src[idx];
}

// concat [save(256) | x(256)] -> 512-wide bf16 hi/lo splits directly (no fp32 intermediate)
__global__ void concat_split_kernel(const float4* __restrict__ save, const float4* __restrict__ x,
                                    __nv_bfloat16* __restrict__ Sh, __nv_bfloat16* __restrict__ Sl,
                                    int N) {
    int idx = blockIdx.x * blockDim.x + threadIdx.x;
    if (idx >= N * 128) return;
    int node = idx >> 7, c = idx & 127;
    float4 v = (c < 64) ? save[(size_t)node * 64 + c] : x[(size_t)node * 64 + (c - 64)];
    uint32_t h0 = pk_hi(v.x, v.y), h1 = pk_hi(v.z, v.w);
    uint32_t l0 = pk_hi(v.x - bf_rt(v.x), v.y - bf_rt(v.y));
    uint32_t l1 = pk_hi(v.z - bf_rt(v.z), v.w - bf_rt(v.w));
    ((uint2*)(Sh + (size_t)node * 512))[c] = make_uint2(h0, h1);
    ((uint2*)(Sl + (size_t)node * 512))[c] = make_uint2(l0, l1);
}

// gelu + layernorm; emits bf16 hi/lo directly
__global__ void gelu_ln_kernel(const float* __restrict__ M, const float* __restrict__ s,
                               const float* __restrict__ b,
                               __nv_bfloat16* __restrict__ Mh, __nv_bfloat16* __restrict__ Ml,
                               int dm, int N) {
    int warp = (blockIdx.x * blockDim.x + threadIdx.x) >> 5;
    int lane = threadIdx.x & 31;
    if (warp >= N) return;
    const float* row = M + (size_t)warp * dm;
    int per = dm >> 5;
    float v[16];
    float sum = 0.f;
    for (int i = 0; i < per; i++) {
        float x = row[i * 32 + lane];
        float g = 0.5f * x * (1.0f + erff(x * 0.70710678118654752f));
        v[i] = g; sum += g;
    }
    #pragma unroll
    for (int o = 16; o > 0; o >>= 1) sum += __shfl_xor_sync(0xFFFFFFFF, sum, o);
    float mu = sum / (float)dm;
    float vs = 0.f;
    for (int i = 0; i < per; i++) { float d = v[i] - mu; vs += d * d; }
    #pragma unroll
    for (int o = 16; o > 0; o >>= 1) vs += __shfl_xor_sync(0xFFFFFFFF, vs, o);
    float inv = rsqrtf(vs / (float)dm + 1e-5f);
    for (int i = 0; i < per; i++) {
        int c = i * 32 + lane;
        float y = (v[i] - mu) * inv * s[c] + b[c];
        __nv_bfloat16 h = __float2bfloat16(y);
        Mh[(size_t)warp * dm + c] = h;
        Ml[(size_t)warp * dm + c] = __float2bfloat16(y - __bfloat162float(h));
    }
}

// ---------------- mma.sync GEMM (MODE 0: edge gather+scatter, MODE 1: dense+tanh) ----------------
// CTA tile 128(M) x 256(N), K chunk 32 bf16, bf16x3 split (hh + hl + lh).
// 512 threads = 16 warps (2x8), warp tile 64x32. Double-buffered cp.async stages.

#define ROWB 80
#define ASPL 10240          // A lo offset (128*80)
#define BOFF 20480          // B hi offset
#define BSPL 20480          // B lo relative offset (256*80)
#define STAGE 61440
#define SMEM_BYTES (1024 + 2 * STAGE)

template<int MODE>
__global__ __launch_bounds__(512, 1)
void mma_gemm(const __nv_bfloat16* __restrict__ Ah, const __nv_bfloat16* __restrict__ Al,
              int strideA, int K,
              const __nv_bfloat16* __restrict__ Bh_, const __nv_bfloat16* __restrict__ Bl_,
              int dout, float* __restrict__ Out,
              const int* __restrict__ src, const int* __restrict__ tgt,
              const float* __restrict__ bias, int Nrows,
              __nv_bfloat16* __restrict__ OutH, __nv_bfloat16* __restrict__ OutL) {
    extern __shared__ char smem[];
    int tid = threadIdx.x;
    int wid = tid >> 5, lane = tid & 31;
    int row0 = blockIdx.x * 128;
    int col0 = blockIdx.z * 256;

    const __nv_bfloat16 *Bh, *Bl;
    int cnt = 0, offT = 0;
    if (MODE == 0) {
        int t = blockIdx.y;
        cnt = g_cnt[t];
        if (row0 >= cnt) return;
        offT = g_off[t];
        Bh = Bh_ + (size_t)t * dout * K;
        Bl = Bl_ + (size_t)t * dout * K;
    } else {
        if (row0 >= Nrows) return;
        Bh = Bh_; Bl = Bl_;
    }

    int* sSrc = (int*)smem;
    int* sTgt = (int*)(smem + 512);
    char* tiles = smem + 1024;
    uint32_t sb = smem_u32(tiles);

    if (MODE == 0 && tid < 128) {
        int r = row0 + tid;
        int sn = 0, tn = -1;
        if (r < cnt) { int e = g_typeEdges[offT + r]; sn = src[e]; tn = tgt[e]; }
        sSrc[tid] = sn; sTgt[tid] = tn;
    }
    __syncthreads();

    // ---- ldmatrix base addresses ----
    int warp_m = wid >> 3, warp_n = wid & 7;
    uint32_t aAddr[4], bAddr[2];
    {
        int r = (lane & 15), hi8 = (lane >> 4) & 1;
        #pragma unroll
        for (int mt = 0; mt < 4; mt++)
            aAddr[mt] = sb + (warp_m * 64 + mt * 16 + r) * ROWB + hi8 * 16;
        int nr = hi8 * 8 + (lane & 7), kq = (lane >> 3) & 1;
        #pragma unroll
        for (int g = 0; g < 2; g++)
            bAddr[g] = sb + BOFF + (warp_n * 32 + g * 16 + nr) * ROWB + kq * 16;
    }

    float acc[4][4][4];
    #pragma unroll
    for (int i = 0; i < 4; i++)
        #pragma unroll
        for (int j = 0; j < 4; j++)
            #pragma unroll
            for (int q = 0; q < 4; q++) acc[i][j][q] = 0.f;

    const int nch = K >> 5;

    // ---- async chunk loader: pure byte movement (state pre-split to bf16) ----
    auto load_chunk = [&](int c) {
        int kt = c * 32;
        uint32_t stg = sb + (c & 1) * STAGE;
        bool useSrc = true; int colb = kt;
        if (MODE == 0) { useSrc = kt < strideA; colb = useSrc ? kt : kt - strideA; }
        #pragma unroll
        for (int i = 0; i < 2; i++) {
            int slot = tid + i * 512;
            int m = slot >> 3, u3 = slot & 7;
            int split = u3 >> 2, u = u3 & 3;
            const __nv_bfloat16* base = split ? Al : Ah;
            const __nv_bfloat16* srcp;
            if (MODE == 0) {
                int node = useSrc ? sSrc[m] : sTgt[m];
                if (node < 0) node = 0;
                srcp = base + (size_t)node * strideA + colb + u * 8;
            } else {
                int r = row0 + m; if (r >= Nrows) r = 0;
                srcp = base + (size_t)r * strideA + kt + u * 8;
            }
            cpa16(stg + split * ASPL + m * ROWB + u * 16, srcp);
        }
        #pragma unroll
        for (int i = 0; i < 4; i++) {
            int slot = tid + i * 512;
            int n = slot >> 3, u3 = slot & 7;
            int split = u3 >> 2, u = u3 & 3;
            const __nv_bfloat16* bs = split ? Bl : Bh;
            cpa16(stg + BOFF + split * BSPL + n * ROWB + u * 16,
                  bs + (size_t)(col0 + n) * K + kt + u * 8);
        }
        asm volatile("cp.async.commit_group;" ::: "memory");
    };

    load_chunk(0);

    for (int c = 0; c < nch; c++) {
        if (c + 1 < nch) {
            load_chunk(c + 1);
            asm volatile("cp.async.wait_group 1;" ::: "memory");
        } else {
            asm volatile("cp.async.wait_group 0;" ::: "memory");
        }
        __syncthreads();
        uint32_t stoff = (c & 1) * STAGE;
        #pragma unroll
        for (int ks = 0; ks < 2; ks++) {
            uint32_t ko = stoff + ks * 32;
            uint32_t bhf[2][4], blf[2][4];
            ldm_x4(bAddr[0] + ko, bhf[0]);
            ldm_x4(bAddr[1] + ko, bhf[1]);
            ldm_x4(bAddr[0] + ko + BSPL, blf[0]);
            ldm_x4(bAddr[1] + ko + BSPL, blf[1]);
            #pragma unroll
            for (int mt = 0; mt < 4; mt++) {
                uint32_t ah[4], al[4];
                ldm_x4(aAddr[mt] + ko, ah);
                ldm_x4(aAddr[mt] + ko + ASPL, al);
                #pragma unroll
                for (int nt = 0; nt < 4; nt++) {
                    const uint32_t* ph = &bhf[nt >> 1][(nt & 1) * 2];
                    const uint32_t* pl = &blf[nt >> 1][(nt & 1) * 2];
                    mma16816(acc[mt][nt], ah, ph);
                    mma16816(acc[mt][nt], ah, pl);
                    mma16816(acc[mt][nt], al, ph);
                }
            }
        }
        __syncthreads();
    }

    // ---- epilogue ----
    #pragma unroll
    for (int mt = 0; mt < 4; mt++) {
        int rl = warp_m * 64 + mt * 16 + (lane >> 2);
        int rh = rl + 8;
        if (MODE == 0) {
            int v1 = sTgt[rl], v2 = sTgt[rh];
            #pragma unroll
            for (int nt = 0; nt < 4; nt++) {
                int c = col0 + warp_n * 32 + nt * 8 + 2 * (lane & 3);
                if (v1 >= 0) red2(&Out[(size_t)v1 * dout + c], acc[mt][nt][0], acc[mt][nt][1]);
                if (v2 >= 0) red2(&Out[(size_t)v2 * dout + c], acc[mt][nt][2], acc[mt][nt][3]);
            }
        } else {
            int g1 = row0 + rl, g2 = row0 + rh;
            #pragma unroll
            for (int nt = 0; nt < 4; nt++) {
                int c = col0 + warp_n * 32 + nt * 8 + 2 * (lane & 3);
                float b0 = bias[c], b1 = bias[c + 1];
                if (g1 < Nrows) {
                    float y0 = tanhf(acc[mt][nt][0] + b0);
                    float y1 = tanhf(acc[mt][nt][1] + b1);
                    Out[(size_t)g1 * dout + c]     = y0;
                    Out[(size_t)g1 * dout + c + 1] = y1;
                    if (OutH) {
                        uint32_t h = pk_hi(y0, y1);
                        uint32_t l = pk_hi(y0 - bf_rt(y0), y1 - bf_rt(y1));
                        *(uint32_t*)(OutH + (size_t)g1 * dout + c) = h;
                        *(uint32_t*)(OutL + (size_t)g1 * dout + c) = l;
                    }
                }
                if (g2 < Nrows) {
                    float y0 = tanhf(acc[mt][nt][2] + b0);
                    float y1 = tanhf(acc[mt][nt][3] + b1);
                    Out[(size_t)g2 * dout + c]     = y0;
                    Out[(size_t)g2 * dout + c + 1] = y1;
                    if (OutH) {
                        uint32_t h = pk_hi(y0, y1);
                        uint32_t l = pk_hi(y0 - bf_rt(y0), y1 - bf_rt(y1));
                        *(uint32_t*)(OutH + (size_t)g2 * dout + c) = h;
                        *(uint32_t*)(OutL + (size_t)g2 * dout + c) = l;
                    }
                }
            }
        }
    }
}

// ---------------- host-side driver ----------------
static void run_gnn_layer(int din, int N, int E,
                          __nv_bfloat16* Sh, __nv_bfloat16* Sl,
                          __nv_bfloat16* Mh, __nv_bfloat16* Ml,
                          const __nv_bfloat16* Weh, const __nv_bfloat16* Wel,
                          const float* ls, const float* lb,
                          const __nv_bfloat16* Wdh, const __nv_bfloat16* Wdl,
                          const float* bias, float* dest, float* Mbuf,
                          __nv_bfloat16* destH, __nv_bfloat16* destL,
                          const int* src, const int* tgt) {
    long long n4 = (long long)N * din / 4;
    clear_f4_kernel<<<4096, 256>>>((float4*)Mbuf, n4);
    // edge GEMM: K=2*din, dout=din (state splits Sh/Sl as gather source)
    dim3 egrid((E + 127) / 128, 4, din > 256 ? din / 256 : 1);
    mma_gemm<0><<<egrid, 512, SMEM_BYTES>>>(Sh, Sl, din, 2 * din, Weh, Wel, din, Mbuf,
                                            src, tgt, nullptr, 0, nullptr, nullptr);
    gelu_ln_kernel<<<(N + 7) / 8, 256>>>(Mbuf, ls, lb, Mh, Ml, din, N);
    // dense: K=din, dout=256; epilogue writes fp32 + (optionally) bf16 splits
    dim3 dgrid((N + 127) / 128, 1, 1);
    mma_gemm<1><<<dgrid, 512, SMEM_BYTES>>>(Mh, Ml, din, din, Wdh, Wdl, 256, dest,
                                            nullptr, nullptr, bias, N, destH, destL);
}

extern "C" void kernel_launch(void* const* d_in, const int* in_sizes, int n_in,
                              void* d_out, int out_size) {
    const int*   ids   = (const int*)d_in[0];
    const int*   te    = (const int*)d_in[1];
    const float* embed = (const float*)d_in[2];
    const float* WeI   = (const float*)d_in[3];
    const float* lsI   = (const float*)d_in[4];
    const float* lbI   = (const float*)d_in[5];
    const float* WdI   = (const float*)d_in[6];
    const float* bdI   = (const float*)d_in[7];
    const float* WeO   = (const float*)d_in[8];
    const float* lsO   = (const float*)d_in[9];
    const float* lbO   = (const float*)d_in[10];
    const float* WdO   = (const float*)d_in[11];
    const float* bdO   = (const float*)d_in[12];
    float* out = (float*)d_out;

    int N = in_sizes[0];
    int E = in_sizes[1] / 3;
    const int* etype = te;
    const int* src   = te + E;
    const int* tgt   = te + 2 * E;

    float *S0, *S1, *M, *SAVE;
    __nv_bfloat16 *Sh, *Sl, *Mh, *Ml;
    __nv_bfloat16 *WeIh, *WeIl, *WeOh, *WeOl, *WdIh, *WdIl, *WdOh, *WdOl;
    cudaGetSymbolAddress((void**)&S0, g_S0);
    cudaGetSymbolAddress((void**)&S1, g_S1);
    cudaGetSymbolAddress((void**)&M,  g_M);
    cudaGetSymbolAddress((void**)&SAVE, g_SAVE);
    cudaGetSymbolAddress((void**)&Sh, g_Sh);
    cudaGetSymbolAddress((void**)&Sl, g_Sl);
    cudaGetSymbolAddress((void**)&Mh, g_Mh);
    cudaGetSymbolAddress((void**)&Ml, g_Ml);
    cudaGetSymbolAddress((void**)&WeIh, g_WeI_h);
    cudaGetSymbolAddress((void**)&WeIl, g_WeI_l);
    cudaGetSymbolAddress((void**)&WeOh, g_WeO_h);
    cudaGetSymbolAddress((void**)&WeOl, g_WeO_l);
    cudaGetSymbolAddress((void**)&WdIh, g_WdI_h);
    cudaGetSymbolAddress((void**)&WdIl, g_WdI_l);
    cudaGetSymbolAddress((void**)&WdOh, g_WdO_h);
    cudaGetSymbolAddress((void**)&WdOl, g_WdO_l);

    cudaFuncSetAttribute(mma_gemm<0>, cudaFuncAttributeMaxDynamicSharedMemorySize, SMEM_BYTES);
    cudaFuncSetAttribute(mma_gemm<1>, cudaFuncAttributeMaxDynamicSharedMemorySize, SMEM_BYTES);

    // --- preprocessing ---
    clear_counts_kernel<<<1, 32>>>();
    count_types_kernel<<<(E + 255) / 256, 256>>>(etype, E);
    offsets_kernel<<<1, 1>>>();
    scatter_types_kernel<<<(E + 255) / 256, 256>>>(etype, E);

    int nWeI = 6 * 4 * 256 * 512, nWeO = 2 * 4 * 512 * 1024;
    int nWdI = 6 * 256 * 256,     nWdO = 2 * 256 * 512;
    conv_bf16_kernel<<<(nWeI + 255) / 256, 256>>>(WeI, WeIh, WeIl, nWeI);
    conv_bf16_kernel<<<(nWeO + 255) / 256, 256>>>(WeO, WeOh, WeOl, nWeO);
    conv_bf16_kernel<<<(nWdI + 255) / 256, 256>>>(WdI, WdIh, WdIl, nWdI);
    conv_bf16_kernel<<<(nWdO + 255) / 256, 256>>>(WdO, WdOh, WdOl, nWdO);

    embed_kernel<<<(N * 64 + 255) / 256, 256>>>((const float4*)embed, ids, (float4*)S0, N);
    split_kernel<<<(N * 64 + 255) / 256, 256>>>((const float4*)S0, (uint2*)Sh, (uint2*)Sl,
                                                (long long)N * 64);

    float* S = S0;
    float* Snext = S1;

    for (int b = 0; b < 2; b++) {
        copy256_kernel<<<(N * 64 + 255) / 256, 256>>>((const float4*)S, (float4*)SAVE, N);
        for (int i = 0; i < 3; i++) {
            int l = 3 * b + i;
            // inner layer: din=256; dense writes splits for next consumer
            run_gnn_layer(256, N, E, Sh, Sl, Mh, Ml,
                          WeIh + (size_t)l * 4 * 256 * 512, WeIl + (size_t)l * 4 * 256 * 512,
                          lsI + (size_t)l * 256, lbI + (size_t)l * 256,
                          WdIh + (size_t)l * 256 * 256, WdIl + (size_t)l * 256 * 256,
                          bdI + (size_t)l * 256,
                          Snext, M, Sh, Sl, src, tgt);
            float* tmp = S; S = Snext; Snext = tmp;
        }
        // concat -> 512-wide bf16 splits directly
        concat_split_kernel<<<(N * 128 + 255) / 256, 256>>>((const float4*)SAVE,
                                                            (const float4*)S, Sh, Sl, N);
        // output layer: din=512
        float* dest = (b == 1) ? out : Snext;
        run_gnn_layer(512, N, E, Sh, Sl, Mh, Ml,
                      WeOh + (size_t)b * 4 * 512 * 1024, WeOl + (size_t)b * 4 * 512 * 1024,
                      lsO + (size_t)b * 512, lbO + (size_t)b * 512,
                      WdOh + (size_t)b * 256 * 512, WdOl + (size_t)b * 256 * 512,
                      bdO + (size_t)b * 256,
                      dest, M,
                      (b == 0) ? Sh : nullptr, (b == 0) ? Sl : nullptr,
                      src, tgt);
        if (b == 0) { float* tmp = S; S = Snext; Snext = tmp; }
    }
}

// round 6
// speedup vs baseline: 2.6087x; 1.0451x over previous
#include <cuda_runtime.h>
#include <cuda_bf16.h>
#include <math.h>
#include <stdint.h>

#define MAXN 100000
#define MAXE 320000

// ---------------- scratch (device globals; no allocs allowed) ----------------
__device__ __align__(16) float g_S0[(size_t)MAXN * 256];
__device__ __align__(16) float g_S1[(size_t)MAXN * 256];
__device__ __align__(16) float g_M [(size_t)MAXN * 512];
__device__ __align__(16) float g_SAVE[(size_t)MAXN * 256];

// bf16 hi/lo state + message splits
__device__ __align__(16) __nv_bfloat16 g_Sh[(size_t)MAXN * 512], g_Sl[(size_t)MAXN * 512];
__device__ __align__(16) __nv_bfloat16 g_Mh[(size_t)MAXN * 512], g_Ml[(size_t)MAXN * 512];

// bf16 hi/lo weight splits (natural [dout][K] layout == col-major B for mma.row.col)
__device__ __align__(16) __nv_bfloat16 g_WeI_h[6 * 4 * 256 * 512],  g_WeI_l[6 * 4 * 256 * 512];
__device__ __align__(16) __nv_bfloat16 g_WeO_h[2 * 4 * 512 * 1024], g_WeO_l[2 * 4 * 512 * 1024];
__device__ __align__(16) __nv_bfloat16 g_WdI_h[6 * 256 * 256],      g_WdI_l[6 * 256 * 256];
__device__ __align__(16) __nv_bfloat16 g_WdO_h[2 * 256 * 512],      g_WdO_l[2 * 256 * 512];

__device__ int g_typeEdges[MAXE];
__device__ int g_cnt[4], g_off[4], g_cur[4];

// ---------------- helpers ----------------
__device__ __forceinline__ uint32_t smem_u32(const void* p) {
    uint32_t a;
    asm("{ .reg .u64 t; cvta.to.shared.u64 t, %1; cvt.u32.u64 %0, t; }" : "=r"(a) : "l"(p));
    return a;
}

__device__ __forceinline__ void ldm_x4(uint32_t addr, uint32_t r[4]) {
    asm volatile("ldmatrix.sync.aligned.m8n8.x4.shared.b16 {%0,%1,%2,%3}, [%4];"
                 : "=r"(r[0]), "=r"(r[1]), "=r"(r[2]), "=r"(r[3]) : "r"(addr));
}

__device__ __forceinline__ void mma16816(float c[4], const uint32_t a[4], const uint32_t b[2]) {
    asm volatile(
        "mma.sync.aligned.m16n8k16.row.col.f32.bf16.bf16.f32 "
        "{%0,%1,%2,%3}, {%4,%5,%6,%7}, {%8,%9}, {%0,%1,%2,%3};"
        : "+f"(c[0]), "+f"(c[1]), "+f"(c[2]), "+f"(c[3])
        : "r"(a[0]), "r"(a[1]), "r"(a[2]), "r"(a[3]), "r"(b[0]), "r"(b[1]));
}

__device__ __forceinline__ void cpa16(uint32_t dst, const void* src) {
    asm volatile("cp.async.cg.shared.global [%0], [%1], 16;" :: "r"(dst), "l"(src) : "memory");
}

// vectorized f32 reduction (PTX ISA 8.1, sm_90+)
__device__ __forceinline__ void red2(float* addr, float a, float b) {
    asm volatile("red.global.add.v2.f32 [%0], {%1, %2};" :: "l"(addr), "f"(a), "f"(b) : "memory");
}

__device__ __forceinline__ uint32_t pk_hi(float a, float b) {
    __nv_bfloat162 t = __floats2bfloat162_rn(a, b);
    return reinterpret_cast<uint32_t&>(t);
}
__device__ __forceinline__ float bf_rt(float a) {
    return __bfloat162float(__float2bfloat16(a));
}

// ---------------- small utility kernels ----------------
__global__ void clear_f4_kernel(float4* p, long long n4) {
    long long i = (long long)blockIdx.x * blockDim.x + threadIdx.x;
    long long stride = (long long)gridDim.x * blockDim.x;
    float4 z = make_float4(0.f, 0.f, 0.f, 0.f);
    for (; i < n4; i += stride) p[i] = z;
}

__global__ void clear_counts_kernel() {
    int i = threadIdx.x;
    if (i < 4) { g_cnt[i] = 0; g_cur[i] = 0; }
}

__global__ void count_types_kernel(const int* __restrict__ etype, int E) {
    int e = blockIdx.x * blockDim.x + threadIdx.x;
    if (e < E) atomicAdd(&g_cnt[etype[e] - 1], 1);
}

__global__ void offsets_kernel() {
    if (threadIdx.x == 0) {
        g_off[0] = 0;
        g_off[1] = g_cnt[0];
        g_off[2] = g_cnt[0] + g_cnt[1];
        g_off[3] = g_cnt[0] + g_cnt[1] + g_cnt[2];
    }
}

__global__ void scatter_types_kernel(const int* __restrict__ etype, int E) {
    int e = blockIdx.x * blockDim.x + threadIdx.x;
    if (e < E) {
        int t = etype[e] - 1;
        int p = atomicAdd(&g_cur[t], 1);
        g_typeEdges[g_off[t] + p] = e;
    }
}

__global__ void conv_bf16_kernel(const float* __restrict__ w, __nv_bfloat16* __restrict__ hi,
                                 __nv_bfloat16* __restrict__ lo, int n) {
    int i = blockIdx.x * blockDim.x + threadIdx.x;
    if (i >= n) return;
    float x = w[i];
    __nv_bfloat16 h = __float2bfloat16(x);
    hi[i] = h;
    lo[i] = __float2bfloat16(x - __bfloat162float(h));
}

// split fp32 state -> bf16 hi/lo (used once, after embed)
__global__ void split_kernel(const float4* __restrict__ S, uint2* __restrict__ Sh,
                             uint2* __restrict__ Sl, long long n4) {
    long long i = (long long)blockIdx.x * blockDim.x + threadIdx.x;
    if (i >= n4) return;
    float4 v = S[i];
    uint32_t h0 = pk_hi(v.x, v.y), h1 = pk_hi(v.z, v.w);
    uint32_t l0 = pk_hi(v.x - bf_rt(v.x), v.y - bf_rt(v.y));
    uint32_t l1 = pk_hi(v.z - bf_rt(v.z), v.w - bf_rt(v.w));
    Sh[i] = make_uint2(h0, h1);
    Sl[i] = make_uint2(l0, l1);
}

__global__ void embed_kernel(const float4* __restrict__ tab, const int* __restrict__ ids,
                             float4* __restrict__ outS, int N) {
    int idx = blockIdx.x * blockDim.x + threadIdx.x;
    if (idx >= N * 64) return;
    int node = idx >> 6, c = idx & 63;
    int r = ids[node];
    outS[(size_t)node * 64 + c] = tab[(size_t)r * 64 + c];
}

__global__ void copy256_kernel(const float4* __restrict__ src, float4* __restrict__ dst, int N) {
    int idx = blockIdx.x * blockDim.x + threadIdx.x;
    if (idx < N * 64) dst[idx] = src[idx];
}

// concat [save(256) | x(256)] -> 512-wide bf16 hi/lo splits directly
__global__ void concat_split_kernel(const float4* __restrict__ save, const float4* __restrict__ x,
                                    __nv_bfloat16* __restrict__ Sh, __nv_bfloat16* __restrict__ Sl,
                                    int N) {
    int idx = blockIdx.x * blockDim.x + threadIdx.x;
    if (idx >= N * 128) return;
    int node = idx >> 7, c = idx & 127;
    float4 v = (c < 64) ? save[(size_t)node * 64 + c] : x[(size_t)node * 64 + (c - 64)];
    uint32_t h0 = pk_hi(v.x, v.y), h1 = pk_hi(v.z, v.w);
    uint32_t l0 = pk_hi(v.x - bf_rt(v.x), v.y - bf_rt(v.y));
    uint32_t l1 = pk_hi(v.z - bf_rt(v.z), v.w - bf_rt(v.w));
    ((uint2*)(Sh + (size_t)node * 512))[c] = make_uint2(h0, h1);
    ((uint2*)(Sl + (size_t)node * 512))[c] = make_uint2(l0, l1);
}

// gelu + layernorm; emits bf16 hi/lo directly
__global__ void gelu_ln_kernel(const float* __restrict__ M, const float* __restrict__ s,
                               const float* __restrict__ b,
                               __nv_bfloat16* __restrict__ Mh, __nv_bfloat16* __restrict__ Ml,
                               int dm, int N) {
    int warp = (blockIdx.x * blockDim.x + threadIdx.x) >> 5;
    int lane = threadIdx.x & 31;
    if (warp >= N) return;
    const float* row = M + (size_t)warp * dm;
    int per = dm >> 5;
    float v[16];
    float sum = 0.f;
    for (int i = 0; i < per; i++) {
        float x = row[i * 32 + lane];
        float g = 0.5f * x * (1.0f + erff(x * 0.70710678118654752f));
        v[i] = g; sum += g;
    }
    #pragma unroll
    for (int o = 16; o > 0; o >>= 1) sum += __shfl_xor_sync(0xFFFFFFFF, sum, o);
    float mu = sum / (float)dm;
    float vs = 0.f;
    for (int i = 0; i < per; i++) { float d = v[i] - mu; vs += d * d; }
    #pragma unroll
    for (int o = 16; o > 0; o >>= 1) vs += __shfl_xor_sync(0xFFFFFFFF, vs, o);
    float inv = rsqrtf(vs / (float)dm + 1e-5f);
    for (int i = 0; i < per; i++) {
        int c = i * 32 + lane;
        float y = (v[i] - mu) * inv * s[c] + b[c];
        __nv_bfloat16 h = __float2bfloat16(y);
        Mh[(size_t)warp * dm + c] = h;
        Ml[(size_t)warp * dm + c] = __float2bfloat16(y - __bfloat162float(h));
    }
}

// ---------------- mma.sync GEMM (MODE 0: edge gather+scatter, MODE 1: dense+tanh) ----------------
// CTA tile 128(M) x 256(N), K chunk 32 bf16, bf16x3 split (hh + hl + lh).
// 512 threads = 16 warps (2x8), warp tile 64x32.
// 3-stage cp.async pipeline, ONE __syncthreads per chunk.

#define ROWB 80
#define ASPL 10240          // A lo offset (128*80)
#define BOFF 20480          // B hi offset
#define BSPL 20480          // B lo relative offset (256*80)
#define STAGE 61440
#define NSTAGE 3
#define SMEM_BYTES (1024 + NSTAGE * STAGE)

template<int MODE>
__global__ __launch_bounds__(512, 1)
void mma_gemm(const __nv_bfloat16* __restrict__ Ah, const __nv_bfloat16* __restrict__ Al,
              int strideA, int K,
              const __nv_bfloat16* __restrict__ Bh_, const __nv_bfloat16* __restrict__ Bl_,
              int dout, float* __restrict__ Out,
              const int* __restrict__ src, const int* __restrict__ tgt,
              const float* __restrict__ bias, int Nrows,
              __nv_bfloat16* __restrict__ OutH, __nv_bfloat16* __restrict__ OutL) {
    extern __shared__ char smem[];
    int tid = threadIdx.x;
    int wid = tid >> 5, lane = tid & 31;
    int row0 = blockIdx.x * 128;
    int col0 = blockIdx.z * 256;

    const __nv_bfloat16 *Bh, *Bl;
    int cnt = 0, offT = 0;
    if (MODE == 0) {
        int t = blockIdx.y;
        cnt = g_cnt[t];
        if (row0 >= cnt) return;
        offT = g_off[t];
        Bh = Bh_ + (size_t)t * dout * K;
        Bl = Bl_ + (size_t)t * dout * K;
    } else {
        if (row0 >= Nrows) return;
        Bh = Bh_; Bl = Bl_;
    }

    int* sSrc = (int*)smem;
    int* sTgt = (int*)(smem + 512);
    char* tiles = smem + 1024;
    uint32_t sb = smem_u32(tiles);

    if (MODE == 0 && tid < 128) {
        int r = row0 + tid;
        int sn = 0, tn = -1;
        if (r < cnt) { int e = g_typeEdges[offT + r]; sn = src[e]; tn = tgt[e]; }
        sSrc[tid] = sn; sTgt[tid] = tn;
    }
    __syncthreads();

    // ---- ldmatrix base addresses ----
    int warp_m = wid >> 3, warp_n = wid & 7;
    uint32_t aAddr[4], bAddr[2];
    {
        int r = (lane & 15), hi8 = (lane >> 4) & 1;
        #pragma unroll
        for (int mt = 0; mt < 4; mt++)
            aAddr[mt] = sb + (warp_m * 64 + mt * 16 + r) * ROWB + hi8 * 16;
        int nr = hi8 * 8 + (lane & 7), kq = (lane >> 3) & 1;
        #pragma unroll
        for (int g = 0; g < 2; g++)
            bAddr[g] = sb + BOFF + (warp_n * 32 + g * 16 + nr) * ROWB + kq * 16;
    }

    float acc[4][4][4];
    #pragma unroll
    for (int i = 0; i < 4; i++)
        #pragma unroll
        for (int j = 0; j < 4; j++)
            #pragma unroll
            for (int q = 0; q < 4; q++) acc[i][j][q] = 0.f;

    const int nch = K >> 5;

    // ---- async chunk loader: pure byte movement (state pre-split to bf16) ----
    auto load_chunk = [&](int c) {
        int kt = c * 32;
        uint32_t stg = sb + (c % NSTAGE) * STAGE;
        bool useSrc = true; int colb = kt;
        if (MODE == 0) { useSrc = kt < strideA; colb = useSrc ? kt : kt - strideA; }
        #pragma unroll
        for (int i = 0; i < 2; i++) {
            int slot = tid + i * 512;
            int m = slot >> 3, u3 = slot & 7;
            int split = u3 >> 2, u = u3 & 3;
            const __nv_bfloat16* base = split ? Al : Ah;
            const __nv_bfloat16* srcp;
            if (MODE == 0) {
                int node = useSrc ? sSrc[m] : sTgt[m];
                if (node < 0) node = 0;
                srcp = base + (size_t)node * strideA + colb + u * 8;
            } else {
                int r = row0 + m; if (r >= Nrows) r = 0;
                srcp = base + (size_t)r * strideA + kt + u * 8;
            }
            cpa16(stg + split * ASPL + m * ROWB + u * 16, srcp);
        }
        #pragma unroll
        for (int i = 0; i < 4; i++) {
            int slot = tid + i * 512;
            int n = slot >> 3, u3 = slot & 7;
            int split = u3 >> 2, u = u3 & 3;
            const __nv_bfloat16* bs = split ? Bl : Bh;
            cpa16(stg + BOFF + split * BSPL + n * ROWB + u * 16,
                  bs + (size_t)(col0 + n) * K + kt + u * 8);
        }
        asm volatile("cp.async.commit_group;" ::: "memory");
    };

    // prologue: stage 2 chunks
    load_chunk(0);
    load_chunk(1);

    for (int c = 0; c < nch; c++) {
        // chunk c complete when at most 1 group (c+1) is still pending
        asm volatile("cp.async.wait_group 1;" ::: "memory");
        __syncthreads();   // also guarantees buffer (c+2)%3 is fully consumed (was chunk c-1)
        if (c + 2 < nch) load_chunk(c + 2);

        uint32_t stoff = (c % NSTAGE) * STAGE;
        #pragma unroll
        for (int ks = 0; ks < 2; ks++) {
            uint32_t ko = stoff + ks * 32;
            uint32_t bhf[2][4], blf[2][4];
            ldm_x4(bAddr[0] + ko, bhf[0]);
            ldm_x4(bAddr[1] + ko, bhf[1]);
            ldm_x4(bAddr[0] + ko + BSPL, blf[0]);
            ldm_x4(bAddr[1] + ko + BSPL, blf[1]);
            #pragma unroll
            for (int mt = 0; mt < 4; mt++) {
                uint32_t ah[4], al[4];
                ldm_x4(aAddr[mt] + ko, ah);
                ldm_x4(aAddr[mt] + ko + ASPL, al);
                #pragma unroll
                for (int nt = 0; nt < 4; nt++) {
                    const uint32_t* ph = &bhf[nt >> 1][(nt & 1) * 2];
                    const uint32_t* pl = &blf[nt >> 1][(nt & 1) * 2];
                    mma16816(acc[mt][nt], ah, ph);
                    mma16816(acc[mt][nt], ah, pl);
                    mma16816(acc[mt][nt], al, ph);
                }
            }
        }
    }

    // ---- epilogue ----
    #pragma unroll
    for (int mt = 0; mt < 4; mt++) {
        int rl = warp_m * 64 + mt * 16 + (lane >> 2);
        int rh = rl + 8;
        if (MODE == 0) {
            int v1 = sTgt[rl], v2 = sTgt[rh];
            #pragma unroll
            for (int nt = 0; nt < 4; nt++) {
                int c = col0 + warp_n * 32 + nt * 8 + 2 * (lane & 3);
                if (v1 >= 0) red2(&Out[(size_t)v1 * dout + c], acc[mt][nt][0], acc[mt][nt][1]);
                if (v2 >= 0) red2(&Out[(size_t)v2 * dout + c], acc[mt][nt][2], acc[mt][nt][3]);
            }
        } else {
            int g1 = row0 + rl, g2 = row0 + rh;
            #pragma unroll
            for (int nt = 0; nt < 4; nt++) {
                int c = col0 + warp_n * 32 + nt * 8 + 2 * (lane & 3);
                float b0 = bias[c], b1 = bias[c + 1];
                if (g1 < Nrows) {
                    float y0 = tanhf(acc[mt][nt][0] + b0);
                    float y1 = tanhf(acc[mt][nt][1] + b1);
                    Out[(size_t)g1 * dout + c]     = y0;
                    Out[(size_t)g1 * dout + c + 1] = y1;
                    if (OutH) {
                        uint32_t h = pk_hi(y0, y1);
                        uint32_t l = pk_hi(y0 - bf_rt(y0), y1 - bf_rt(y1));
                        *(uint32_t*)(OutH + (size_t)g1 * dout + c) = h;
                        *(uint32_t*)(OutL + (size_t)g1 * dout + c) = l;
                    }
                }
                if (g2 < Nrows) {
                    float y0 = tanhf(acc[mt][nt][2] + b0);
                    float y1 = tanhf(acc[mt][nt][3] + b1);
                    Out[(size_t)g2 * dout + c]     = y0;
                    Out[(size_t)g2 * dout + c + 1] = y1;
                    if (OutH) {
                        uint32_t h = pk_hi(y0, y1);
                        uint32_t l = pk_hi(y0 - bf_rt(y0), y1 - bf_rt(y1));
                        *(uint32_t*)(OutH + (size_t)g2 * dout + c) = h;
                        *(uint32_t*)(OutL + (size_t)g2 * dout + c) = l;
                    }
                }
            }
        }
    }
}

// ---------------- host-side driver ----------------
static void run_gnn_layer(int din, int N, int E,
                          __nv_bfloat16* Sh, __nv_bfloat16* Sl,
                          __nv_bfloat16* Mh, __nv_bfloat16* Ml,
                          const __nv_bfloat16* Weh, const __nv_bfloat16* Wel,
                          const float* ls, const float* lb,
                          const __nv_bfloat16* Wdh, const __nv_bfloat16* Wdl,
                          const float* bias, float* dest, float* Mbuf,
                          __nv_bfloat16* destH, __nv_bfloat16* destL,
                          const int* src, const int* tgt) {
    long long n4 = (long long)N * din / 4;
    clear_f4_kernel<<<4096, 256>>>((float4*)Mbuf, n4);
    dim3 egrid((E + 127) / 128, 4, din > 256 ? din / 256 : 1);
    mma_gemm<0><<<egrid, 512, SMEM_BYTES>>>(Sh, Sl, din, 2 * din, Weh, Wel, din, Mbuf,
                                            src, tgt, nullptr, 0, nullptr, nullptr);
    gelu_ln_kernel<<<(N + 7) / 8, 256>>>(Mbuf, ls, lb, Mh, Ml, din, N);
    dim3 dgrid((N + 127) / 128, 1, 1);
    mma_gemm<1><<<dgrid, 512, SMEM_BYTES>>>(Mh, Ml, din, din, Wdh, Wdl, 256, dest,
                                            nullptr, nullptr, bias, N, destH, destL);
}

extern "C" void kernel_launch(void* const* d_in, const int* in_sizes, int n_in,
                              void* d_out, int out_size) {
    const int*   ids   = (const int*)d_in[0];
    const int*   te    = (const int*)d_in[1];
    const float* embed = (const float*)d_in[2];
    const float* WeI   = (const float*)d_in[3];
    const float* lsI   = (const float*)d_in[4];
    const float* lbI   = (const float*)d_in[5];
    const float* WdI   = (const float*)d_in[6];
    const float* bdI   = (const float*)d_in[7];
    const float* WeO   = (const float*)d_in[8];
    const float* lsO   = (const float*)d_in[9];
    const float* lbO   = (const float*)d_in[10];
    const float* WdO   = (const float*)d_in[11];
    const float* bdO   = (const float*)d_in[12];
    float* out = (float*)d_out;

    int N = in_sizes[0];
    int E = in_sizes[1] / 3;
    const int* etype = te;
    const int* src   = te + E;
    const int* tgt   = te + 2 * E;

    float *S0, *S1, *M, *SAVE;
    __nv_bfloat16 *Sh, *Sl, *Mh, *Ml;
    __nv_bfloat16 *WeIh, *WeIl, *WeOh, *WeOl, *WdIh, *WdIl, *WdOh, *WdOl;
    cudaGetSymbolAddress((void**)&S0, g_S0);
    cudaGetSymbolAddress((void**)&S1, g_S1);
    cudaGetSymbolAddress((void**)&M,  g_M);
    cudaGetSymbolAddress((void**)&SAVE, g_SAVE);
    cudaGetSymbolAddress((void**)&Sh, g_Sh);
    cudaGetSymbolAddress((void**)&Sl, g_Sl);
    cudaGetSymbolAddress((void**)&Mh, g_Mh);
    cudaGetSymbolAddress((void**)&Ml, g_Ml);
    cudaGetSymbolAddress((void**)&WeIh, g_WeI_h);
    cudaGetSymbolAddress((void**)&WeIl, g_WeI_l);
    cudaGetSymbolAddress((void**)&WeOh, g_WeO_h);
    cudaGetSymbolAddress((void**)&WeOl, g_WeO_l);
    cudaGetSymbolAddress((void**)&WdIh, g_WdI_h);
    cudaGetSymbolAddress((void**)&WdIl, g_WdI_l);
    cudaGetSymbolAddress((void**)&WdOh, g_WdO_h);
    cudaGetSymbolAddress((void**)&WdOl, g_WdO_l);

    cudaFuncSetAttribute(mma_gemm<0>, cudaFuncAttributeMaxDynamicSharedMemorySize, SMEM_BYTES);
    cudaFuncSetAttribute(mma_gemm<1>, cudaFuncAttributeMaxDynamicSharedMemorySize, SMEM_BYTES);

    // --- preprocessing ---
    clear_counts_kernel<<<1, 32>>>();
    count_types_kernel<<<(E + 255) / 256, 256>>>(etype, E);
    offsets_kernel<<<1, 1>>>();
    scatter_types_kernel<<<(E + 255) / 256, 256>>>(etype, E);

    int nWeI = 6 * 4 * 256 * 512, nWeO = 2 * 4 * 512 * 1024;
    int nWdI = 6 * 256 * 256,     nWdO = 2 * 256 * 512;
    conv_bf16_kernel<<<(nWeI + 255) / 256, 256>>>(WeI, WeIh, WeIl, nWeI);
    conv_bf16_kernel<<<(nWeO + 255) / 256, 256>>>(WeO, WeOh, WeOl, nWeO);
    conv_bf16_kernel<<<(nWdI + 255) / 256, 256>>>(WdI, WdIh, WdIl, nWdI);
    conv_bf16_kernel<<<(nWdO + 255) / 256, 256>>>(WdO, WdOh, WdOl, nWdO);

    embed_kernel<<<(N * 64 + 255) / 256, 256>>>((const float4*)embed, ids, (float4*)S0, N);
    split_kernel<<<(N * 64 + 255) / 256, 256>>>((const float4*)S0, (uint2*)Sh, (uint2*)Sl,
                                                (long long)N * 64);

    float* S = S0;
    float* Snext = S1;

    for (int b = 0; b < 2; b++) {
        copy256_kernel<<<(N * 64 + 255) / 256, 256>>>((const float4*)S, (float4*)SAVE, N);
        for (int i = 0; i < 3; i++) {
            int l = 3 * b + i;
            run_gnn_layer(256, N, E, Sh, Sl, Mh, Ml,
                          WeIh + (size_t)l * 4 * 256 * 512, WeIl + (size_t)l * 4 * 256 * 512,
                          lsI + (size_t)l * 256, lbI + (size_t)l * 256,
                          WdIh + (size_t)l * 256 * 256, WdIl + (size_t)l * 256 * 256,
                          bdI + (size_t)l * 256,
                          Snext, M, Sh, Sl, src, tgt);
            float* tmp = S; S = Snext; Snext = tmp;
        }
        concat_split_kernel<<<(N * 128 + 255) / 256, 256>>>((const float4*)SAVE,
                                                            (const float4*)S, Sh, Sl, N);
        float* dest = (b == 1) ? out : Snext;
        run_gnn_layer(512, N, E, Sh, Sl, Mh, Ml,
                      WeOh + (size_t)b * 4 * 512 * 1024, WeOl + (size_t)b * 4 * 512 * 1024,
                      lsO + (size_t)b * 512, lbO + (size_t)b * 512,
                      WdOh + (size_t)b * 256 * 512, WdOl + (size_t)b * 256 * 512,
                      bdO + (size_t)b * 256,
                      dest, M,
                      (b == 0) ? Sh : nullptr, (b == 0) ? Sl : nullptr,
                      src, tgt);
        if (b == 0) { float* tmp = S; S = Snext; Snext = tmp; }
    }
}

// round 7
// speedup vs baseline: 3.5074x; 1.3445x over previous
#include <cuda_runtime.h>
#include <cuda_fp16.h>
#include <math.h>
#include <stdint.h>

#define MAXN 100000
#define MAXE 320000

// ---------------- scratch (device globals; no allocs allowed) ----------------
__device__ __align__(16) float g_S0[(size_t)MAXN * 256];
__device__ __align__(16) float g_S1[(size_t)MAXN * 256];
__device__ __align__(16) float g_M [(size_t)MAXN * 512];
__device__ __align__(16) float g_SAVE[(size_t)MAXN * 256];

// fp16 state + message (single precision copy; A-side of GEMMs)
__device__ __align__(16) __half g_Sh[(size_t)MAXN * 512];
__device__ __align__(16) __half g_Mh[(size_t)MAXN * 512];

// fp16 hi/lo weight splits (natural [dout][K] layout == col-major B for mma.row.col)
__device__ __align__(16) __half g_WeI_h[6 * 4 * 256 * 512],  g_WeI_l[6 * 4 * 256 * 512];
__device__ __align__(16) __half g_WeO_h[2 * 4 * 512 * 1024], g_WeO_l[2 * 4 * 512 * 1024];
__device__ __align__(16) __half g_WdI_h[6 * 256 * 256],      g_WdI_l[6 * 256 * 256];
__device__ __align__(16) __half g_WdO_h[2 * 256 * 512],      g_WdO_l[2 * 256 * 512];

__device__ int g_typeEdges[MAXE];
__device__ int g_cnt[4], g_off[4], g_cur[4];

// ---------------- helpers ----------------
__device__ __forceinline__ uint32_t smem_u32(const void* p) {
    uint32_t a;
    asm("{ .reg .u64 t; cvta.to.shared.u64 t, %1; cvt.u32.u64 %0, t; }" : "=r"(a) : "l"(p));
    return a;
}

__device__ __forceinline__ void ldm_x4(uint32_t addr, uint32_t r[4]) {
    asm volatile("ldmatrix.sync.aligned.m8n8.x4.shared.b16 {%0,%1,%2,%3}, [%4];"
                 : "=r"(r[0]), "=r"(r[1]), "=r"(r[2]), "=r"(r[3]) : "r"(addr));
}

__device__ __forceinline__ void mma16816(float c[4], const uint32_t a[4], const uint32_t b[2]) {
    asm volatile(
        "mma.sync.aligned.m16n8k16.row.col.f32.f16.f16.f32 "
        "{%0,%1,%2,%3}, {%4,%5,%6,%7}, {%8,%9}, {%0,%1,%2,%3};"
        : "+f"(c[0]), "+f"(c[1]), "+f"(c[2]), "+f"(c[3])
        : "r"(a[0]), "r"(a[1]), "r"(a[2]), "r"(a[3]), "r"(b[0]), "r"(b[1]));
}

__device__ __forceinline__ void cpa16(uint32_t dst, const void* src) {
    asm volatile("cp.async.cg.shared.global [%0], [%1], 16;" :: "r"(dst), "l"(src) : "memory");
}

// vectorized f32 reduction (PTX ISA 8.1, sm_90+)
__device__ __forceinline__ void red2(float* addr, float a, float b) {
    asm volatile("red.global.add.v2.f32 [%0], {%1, %2};" :: "l"(addr), "f"(a), "f"(b) : "memory");
}

__device__ __forceinline__ uint32_t pk_h2(float a, float b) {
    __half2 t = __floats2half2_rn(a, b);
    return reinterpret_cast<uint32_t&>(t);
}

// ---------------- small utility kernels ----------------
__global__ void clear_f4_kernel(float4* p, long long n4) {
    long long i = (long long)blockIdx.x * blockDim.x + threadIdx.x;
    long long stride = (long long)gridDim.x * blockDim.x;
    float4 z = make_float4(0.f, 0.f, 0.f, 0.f);
    for (; i < n4; i += stride) p[i] = z;
}

__global__ void clear_counts_kernel() {
    int i = threadIdx.x;
    if (i < 4) { g_cnt[i] = 0; g_cur[i] = 0; }
}

__global__ void count_types_kernel(const int* __restrict__ etype, int E) {
    int e = blockIdx.x * blockDim.x + threadIdx.x;
    if (e < E) atomicAdd(&g_cnt[etype[e] - 1], 1);
}

__global__ void offsets_kernel() {
    if (threadIdx.x == 0) {
        g_off[0] = 0;
        g_off[1] = g_cnt[0];
        g_off[2] = g_cnt[0] + g_cnt[1];
        g_off[3] = g_cnt[0] + g_cnt[1] + g_cnt[2];
    }
}

__global__ void scatter_types_kernel(const int* __restrict__ etype, int E) {
    int e = blockIdx.x * blockDim.x + threadIdx.x;
    if (e < E) {
        int t = etype[e] - 1;
        int p = atomicAdd(&g_cur[t], 1);
        g_typeEdges[g_off[t] + p] = e;
    }
}

// weights: fp32 -> fp16 hi + fp16 lo (residual)
__global__ void conv_f16_kernel(const float* __restrict__ w, __half* __restrict__ hi,
                                __half* __restrict__ lo, int n) {
    int i = blockIdx.x * blockDim.x + threadIdx.x;
    if (i >= n) return;
    float x = w[i];
    __half h = __float2half_rn(x);
    hi[i] = h;
    lo[i] = __float2half_rn(x - __half2float(h));
}

// state: fp32 -> single fp16
__global__ void tof16_kernel(const float4* __restrict__ S, uint2* __restrict__ Sh, long long n4) {
    long long i = (long long)blockIdx.x * blockDim.x + threadIdx.x;
    if (i >= n4) return;
    float4 v = S[i];
    Sh[i] = make_uint2(pk_h2(v.x, v.y), pk_h2(v.z, v.w));
}

__global__ void embed_kernel(const float4* __restrict__ tab, const int* __restrict__ ids,
                             float4* __restrict__ outS, int N) {
    int idx = blockIdx.x * blockDim.x + threadIdx.x;
    if (idx >= N * 64) return;
    int node = idx >> 6, c = idx & 63;
    int r = ids[node];
    outS[(size_t)node * 64 + c] = tab[(size_t)r * 64 + c];
}

__global__ void copy256_kernel(const float4* __restrict__ src, float4* __restrict__ dst, int N) {
    int idx = blockIdx.x * blockDim.x + threadIdx.x;
    if (idx < N * 64) dst[idx] = src[idx];
}

// concat [save(256) | x(256)] -> 512-wide fp16 state
__global__ void concat_f16_kernel(const float4* __restrict__ save, const float4* __restrict__ x,
                                  __half* __restrict__ Sh, int N) {
    int idx = blockIdx.x * blockDim.x + threadIdx.x;
    if (idx >= N * 128) return;
    int node = idx >> 7, c = idx & 127;
    float4 v = (c < 64) ? save[(size_t)node * 64 + c] : x[(size_t)node * 64 + (c - 64)];
    ((uint2*)(Sh + (size_t)node * 512))[c] = make_uint2(pk_h2(v.x, v.y), pk_h2(v.z, v.w));
}

// gelu + layernorm; emits fp16 directly
__global__ void gelu_ln_kernel(const float* __restrict__ M, const float* __restrict__ s,
                               const float* __restrict__ b,
                               __half* __restrict__ Mh, int dm, int N) {
    int warp = (blockIdx.x * blockDim.x + threadIdx.x) >> 5;
    int lane = threadIdx.x & 31;
    if (warp >= N) return;
    const float* row = M + (size_t)warp * dm;
    int per = dm >> 5;
    float v[16];
    float sum = 0.f;
    for (int i = 0; i < per; i++) {
        float x = row[i * 32 + lane];
        float g = 0.5f * x * (1.0f + erff(x * 0.70710678118654752f));
        v[i] = g; sum += g;
    }
    #pragma unroll
    for (int o = 16; o > 0; o >>= 1) sum += __shfl_xor_sync(0xFFFFFFFF, sum, o);
    float mu = sum / (float)dm;
    float vs = 0.f;
    for (int i = 0; i < per; i++) { float d = v[i] - mu; vs += d * d; }
    #pragma unroll
    for (int o = 16; o > 0; o >>= 1) vs += __shfl_xor_sync(0xFFFFFFFF, vs, o);
    float inv = rsqrtf(vs / (float)dm + 1e-5f);
    for (int i = 0; i < per; i++) {
        int c = i * 32 + lane;
        float y = (v[i] - mu) * inv * s[c] + b[c];
        Mh[(size_t)warp * dm + c] = __float2half_rn(y);
    }
}

// ---------------- mma.sync GEMM (MODE 0: edge gather+scatter, MODE 1: dense+tanh) ----------------
// fp16 2-term: C = A_f16 @ (Bh + Bl).  CTA tile 128(M) x 256(N), K chunk 32.
// 512 threads = 16 warps (2x8), warp tile 64x32. 4-stage cp.async pipeline.

#define ROWB 80
#define BOFF 10240          // B hi offset (A = 128*80)
#define BSPL 20480          // B lo relative offset (256*80)
#define STAGE 51200
#define NSTAGE 4
#define SMEM_BYTES (1024 + NSTAGE * STAGE)

template<int MODE>
__global__ __launch_bounds__(512, 1)
void mma_gemm(const __half* __restrict__ Ah, int strideA, int K,
              const __half* __restrict__ Bh_, const __half* __restrict__ Bl_,
              int dout, float* __restrict__ Out,
              const int* __restrict__ src, const int* __restrict__ tgt,
              const float* __restrict__ bias, int Nrows,
              __half* __restrict__ OutH) {
    extern __shared__ char smem[];
    int tid = threadIdx.x;
    int wid = tid >> 5, lane = tid & 31;
    int row0 = blockIdx.x * 128;
    int col0 = blockIdx.z * 256;

    const __half *Bh, *Bl;
    int cnt = 0, offT = 0;
    if (MODE == 0) {
        int t = blockIdx.y;
        cnt = g_cnt[t];
        if (row0 >= cnt) return;
        offT = g_off[t];
        Bh = Bh_ + (size_t)t * dout * K;
        Bl = Bl_ + (size_t)t * dout * K;
    } else {
        if (row0 >= Nrows) return;
        Bh = Bh_; Bl = Bl_;
    }

    int* sSrc = (int*)smem;
    int* sTgt = (int*)(smem + 512);
    char* tiles = smem + 1024;
    uint32_t sb = smem_u32(tiles);

    if (MODE == 0 && tid < 128) {
        int r = row0 + tid;
        int sn = 0, tn = -1;
        if (r < cnt) { int e = g_typeEdges[offT + r]; sn = src[e]; tn = tgt[e]; }
        sSrc[tid] = sn; sTgt[tid] = tn;
    }
    __syncthreads();

    // ---- ldmatrix base addresses ----
    int warp_m = wid >> 3, warp_n = wid & 7;
    uint32_t aAddr[4], bAddr[2];
    {
        int r = (lane & 15), hi8 = (lane >> 4) & 1;
        #pragma unroll
        for (int mt = 0; mt < 4; mt++)
            aAddr[mt] = sb + (warp_m * 64 + mt * 16 + r) * ROWB + hi8 * 16;
        int nr = hi8 * 8 + (lane & 7), kq = (lane >> 3) & 1;
        #pragma unroll
        for (int g = 0; g < 2; g++)
            bAddr[g] = sb + BOFF + (warp_n * 32 + g * 16 + nr) * ROWB + kq * 16;
    }

    float acc[4][4][4];
    #pragma unroll
    for (int i = 0; i < 4; i++)
        #pragma unroll
        for (int j = 0; j < 4; j++)
            #pragma unroll
            for (int q = 0; q < 4; q++) acc[i][j][q] = 0.f;

    const int nch = K >> 5;

    // ---- async chunk loader ----
    auto load_chunk = [&](int c) {
        int kt = c * 32;
        uint32_t stg = sb + (c % NSTAGE) * STAGE;
        bool useSrc = true; int colb = kt;
        if (MODE == 0) { useSrc = kt < strideA; colb = useSrc ? kt : kt - strideA; }
        // A: 128 rows x 64B = 512 x 16B (single fp16)
        {
            int m = tid >> 2, u = tid & 3;
            const __half* srcp;
            if (MODE == 0) {
                int node = useSrc ? sSrc[m] : sTgt[m];
                if (node < 0) node = 0;
                srcp = Ah + (size_t)node * strideA + colb + u * 8;
            } else {
                int r = row0 + m; if (r >= Nrows) r = 0;
                srcp = Ah + (size_t)r * strideA + kt + u * 8;
            }
            cpa16(stg + m * ROWB + u * 16, srcp);
        }
        // B hi/lo: 2 x 256 rows x 64B = 2048 x 16B
        #pragma unroll
        for (int i = 0; i < 4; i++) {
            int slot = tid + i * 512;
            int split = slot >> 10, s2 = slot & 1023;
            int n = s2 >> 2, u = s2 & 3;
            const __half* bs = split ? Bl : Bh;
            cpa16(stg + BOFF + split * BSPL + n * ROWB + u * 16,
                  bs + (size_t)(col0 + n) * K + kt + u * 8);
        }
        asm volatile("cp.async.commit_group;" ::: "memory");
    };

    // prologue: stage 3 chunks (nch >= 8 always here)
    load_chunk(0);
    load_chunk(1);
    load_chunk(2);

    for (int c = 0; c < nch; c++) {
        // constant pending=3 before wait: chunks c, c+1, c+2 (empty groups pad the tail)
        asm volatile("cp.async.wait_group 2;" ::: "memory");
        __syncthreads();
        if (c + 3 < nch) load_chunk(c + 3);
        else asm volatile("cp.async.commit_group;" ::: "memory");  // empty group keeps count stable

        uint32_t stoff = (c % NSTAGE) * STAGE;
        #pragma unroll
        for (int ks = 0; ks < 2; ks++) {
            uint32_t ko = stoff + ks * 32;
            uint32_t bhf[2][4], blf[2][4];
            ldm_x4(bAddr[0] + ko, bhf[0]);
            ldm_x4(bAddr[1] + ko, bhf[1]);
            ldm_x4(bAddr[0] + ko + BSPL, blf[0]);
            ldm_x4(bAddr[1] + ko + BSPL, blf[1]);
            #pragma unroll
            for (int mt = 0; mt < 4; mt++) {
                uint32_t ah[4];
                ldm_x4(aAddr[mt] + ko, ah);
                #pragma unroll
                for (int nt = 0; nt < 4; nt++) {
                    const uint32_t* ph = &bhf[nt >> 1][(nt & 1) * 2];
                    const uint32_t* pl = &blf[nt >> 1][(nt & 1) * 2];
                    mma16816(acc[mt][nt], ah, ph);
                    mma16816(acc[mt][nt], ah, pl);
                }
            }
        }
    }

    // ---- epilogue ----
    #pragma unroll
    for (int mt = 0; mt < 4; mt++) {
        int rl = warp_m * 64 + mt * 16 + (lane >> 2);
        int rh = rl + 8;
        if (MODE == 0) {
            int v1 = sTgt[rl], v2 = sTgt[rh];
            #pragma unroll
            for (int nt = 0; nt < 4; nt++) {
                int c = col0 + warp_n * 32 + nt * 8 + 2 * (lane & 3);
                if (v1 >= 0) red2(&Out[(size_t)v1 * dout + c], acc[mt][nt][0], acc[mt][nt][1]);
                if (v2 >= 0) red2(&Out[(size_t)v2 * dout + c], acc[mt][nt][2], acc[mt][nt][3]);
            }
        } else {
            int g1 = row0 + rl, g2 = row0 + rh;
            #pragma unroll
            for (int nt = 0; nt < 4; nt++) {
                int c = col0 + warp_n * 32 + nt * 8 + 2 * (lane & 3);
                float b0 = bias[c], b1 = bias[c + 1];
                if (g1 < Nrows) {
                    float y0 = tanhf(acc[mt][nt][0] + b0);
                    float y1 = tanhf(acc[mt][nt][1] + b1);
                    Out[(size_t)g1 * dout + c]     = y0;
                    Out[(size_t)g1 * dout + c + 1] = y1;
                    if (OutH) *(uint32_t*)(OutH + (size_t)g1 * dout + c) = pk_h2(y0, y1);
                }
                if (g2 < Nrows) {
                    float y0 = tanhf(acc[mt][nt][2] + b0);
                    float y1 = tanhf(acc[mt][nt][3] + b1);
                    Out[(size_t)g2 * dout + c]     = y0;
                    Out[(size_t)g2 * dout + c + 1] = y1;
                    if (OutH) *(uint32_t*)(OutH + (size_t)g2 * dout + c) = pk_h2(y0, y1);
                }
            }
        }
    }
}

// ---------------- host-side driver ----------------
static void run_gnn_layer(int din, int N, int E,
                          __half* Sh, __half* Mh,
                          const __half* Weh, const __half* Wel,
                          const float* ls, const float* lb,
                          const __half* Wdh, const __half* Wdl,
                          const float* bias, float* dest, float* Mbuf,
                          __half* destH,
                          const int* src, const int* tgt) {
    long long n4 = (long long)N * din / 4;
    clear_f4_kernel<<<4096, 256>>>((float4*)Mbuf, n4);
    dim3 egrid((E + 127) / 128, 4, din > 256 ? din / 256 : 1);
    mma_gemm<0><<<egrid, 512, SMEM_BYTES>>>(Sh, din, 2 * din, Weh, Wel, din, Mbuf,
                                            src, tgt, nullptr, 0, nullptr);
    gelu_ln_kernel<<<(N + 7) / 8, 256>>>(Mbuf, ls, lb, Mh, din, N);
    dim3 dgrid((N + 127) / 128, 1, 1);
    mma_gemm<1><<<dgrid, 512, SMEM_BYTES>>>(Mh, din, din, Wdh, Wdl, 256, dest,
                                            nullptr, nullptr, bias, N, destH);
}

extern "C" void kernel_launch(void* const* d_in, const int* in_sizes, int n_in,
                              void* d_out, int out_size) {
    const int*   ids   = (const int*)d_in[0];
    const int*   te    = (const int*)d_in[1];
    const float* embed = (const float*)d_in[2];
    const float* WeI   = (const float*)d_in[3];
    const float* lsI   = (const float*)d_in[4];
    const float* lbI   = (const float*)d_in[5];
    const float* WdI   = (const float*)d_in[6];
    const float* bdI   = (const float*)d_in[7];
    const float* WeO   = (const float*)d_in[8];
    const float* lsO   = (const float*)d_in[9];
    const float* lbO   = (const float*)d_in[10];
    const float* WdO   = (const float*)d_in[11];
    const float* bdO   = (const float*)d_in[12];
    float* out = (float*)d_out;

    int N = in_sizes[0];
    int E = in_sizes[1] / 3;
    const int* etype = te;
    const int* src   = te + E;
    const int* tgt   = te + 2 * E;

    float *S0, *S1, *M, *SAVE;
    __half *Sh, *Mh;
    __half *WeIh, *WeIl, *WeOh, *WeOl, *WdIh, *WdIl, *WdOh, *WdOl;
    cudaGetSymbolAddress((void**)&S0, g_S0);
    cudaGetSymbolAddress((void**)&S1, g_S1);
    cudaGetSymbolAddress((void**)&M,  g_M);
    cudaGetSymbolAddress((void**)&SAVE, g_SAVE);
    cudaGetSymbolAddress((void**)&Sh, g_Sh);
    cudaGetSymbolAddress((void**)&Mh, g_Mh);
    cudaGetSymbolAddress((void**)&WeIh, g_WeI_h);
    cudaGetSymbolAddress((void**)&WeIl, g_WeI_l);
    cudaGetSymbolAddress((void**)&WeOh, g_WeO_h);
    cudaGetSymbolAddress((void**)&WeOl, g_WeO_l);
    cudaGetSymbolAddress((void**)&WdIh, g_WdI_h);
    cudaGetSymbolAddress((void**)&WdIl, g_WdI_l);
    cudaGetSymbolAddress((void**)&WdOh, g_WdO_h);
    cudaGetSymbolAddress((void**)&WdOl, g_WdO_l);

    cudaFuncSetAttribute(mma_gemm<0>, cudaFuncAttributeMaxDynamicSharedMemorySize, SMEM_BYTES);
    cudaFuncSetAttribute(mma_gemm<1>, cudaFuncAttributeMaxDynamicSharedMemorySize, SMEM_BYTES);

    // --- preprocessing ---
    clear_counts_kernel<<<1, 32>>>();
    count_types_kernel<<<(E + 255) / 256, 256>>>(etype, E);
    offsets_kernel<<<1, 1>>>();
    scatter_types_kernel<<<(E + 255) / 256, 256>>>(etype, E);

    int nWeI = 6 * 4 * 256 * 512, nWeO = 2 * 4 * 512 * 1024;
    int nWdI = 6 * 256 * 256,     nWdO = 2 * 256 * 512;
    conv_f16_kernel<<<(nWeI + 255) / 256, 256>>>(WeI, WeIh, WeIl, nWeI);
    conv_f16_kernel<<<(nWeO + 255) / 256, 256>>>(WeO, WeOh, WeOl, nWeO);
    conv_f16_kernel<<<(nWdI + 255) / 256, 256>>>(WdI, WdIh, WdIl, nWdI);
    conv_f16_kernel<<<(nWdO + 255) / 256, 256>>>(WdO, WdOh, WdOl, nWdO);

    embed_kernel<<<(N * 64 + 255) / 256, 256>>>((const float4*)embed, ids, (float4*)S0, N);
    tof16_kernel<<<(N * 64 + 255) / 256, 256>>>((const float4*)S0, (uint2*)Sh,
                                                (long long)N * 64);

    float* S = S0;
    float* Snext = S1;

    for (int b = 0; b < 2; b++) {
        copy256_kernel<<<(N * 64 + 255) / 256, 256>>>((const float4*)S, (float4*)SAVE, N);
        for (int i = 0; i < 3; i++) {
            int l = 3 * b + i;
            run_gnn_layer(256, N, E, Sh, Mh,
                          WeIh + (size_t)l * 4 * 256 * 512, WeIl + (size_t)l * 4 * 256 * 512,
                          lsI + (size_t)l * 256, lbI + (size_t)l * 256,
                          WdIh + (size_t)l * 256 * 256, WdIl + (size_t)l * 256 * 256,
                          bdI + (size_t)l * 256,
                          Snext, M, Sh, src, tgt);
            float* tmp = S; S = Snext; Snext = tmp;
        }
        concat_f16_kernel<<<(N * 128 + 255) / 256, 256>>>((const float4*)SAVE,
                                                          (const float4*)S, Sh, N);
        float* dest = (b == 1) ? out : Snext;
        run_gnn_layer(512, N, E, Sh, Mh,
                      WeOh + (size_t)b * 4 * 512 * 1024, WeOl + (size_t)b * 4 * 512 * 1024,
                      lsO + (size_t)b * 512, lbO + (size_t)b * 512,
                      WdOh + (size_t)b * 256 * 512, WdOl + (size_t)b * 256 * 512,
                      bdO + (size_t)b * 256,
                      dest, M,
                      (b == 0) ? Sh : nullptr,
                      src, tgt);
        if (b == 0) { float* tmp = S; S = Snext; Snext = tmp; }
    }
}

// round 9
// speedup vs baseline: 3.5783x; 1.0202x over previous
#include <cuda_runtime.h>
#include <cuda_fp16.h>
#include <math.h>
#include <stdint.h>

#define MAXN 100000
#define MAXE 320000

// ---------------- scratch (device globals; no allocs allowed) ----------------
__device__ __align__(16) float g_S0[(size_t)MAXN * 256];
__device__ __align__(16) float g_S1[(size_t)MAXN * 256];
__device__ __align__(16) float g_M [(size_t)MAXN * 512];

// fp16 state + message (single precision copy; A-side of GEMMs)
__device__ __align__(16) __half g_Sh[(size_t)MAXN * 512];
__device__ __align__(16) __half g_Mh[(size_t)MAXN * 512];

// fp16 hi/lo weight splits (natural [dout][K] layout == col-major B for mma.row.col)
__device__ __align__(16) __half g_WeI_h[6 * 4 * 256 * 512],  g_WeI_l[6 * 4 * 256 * 512];
__device__ __align__(16) __half g_WeO_h[2 * 4 * 512 * 1024], g_WeO_l[2 * 4 * 512 * 1024];
__device__ __align__(16) __half g_WdI_h[6 * 256 * 256],      g_WdI_l[6 * 256 * 256];
__device__ __align__(16) __half g_WdO_h[2 * 256 * 512],      g_WdO_l[2 * 256 * 512];

__device__ int g_typeEdges[MAXE];
__device__ int g_cnt[4], g_off[4], g_cur[4];

// ---------------- helpers ----------------
__device__ __forceinline__ uint32_t smem_u32(const void* p) {
    uint32_t a;
    asm("{ .reg .u64 t; cvta.to.shared.u64 t, %1; cvt.u32.u64 %0, t; }" : "=r"(a) : "l"(p));
    return a;
}

__device__ __forceinline__ void ldm_x4(uint32_t addr, uint32_t r[4]) {
    asm volatile("ldmatrix.sync.aligned.m8n8.x4.shared.b16 {%0,%1,%2,%3}, [%4];"
                 : "=r"(r[0]), "=r"(r[1]), "=r"(r[2]), "=r"(r[3]) : "r"(addr));
}

__device__ __forceinline__ void mma16816(float c[4], const uint32_t a[4], const uint32_t b[2]) {
    asm volatile(
        "mma.sync.aligned.m16n8k16.row.col.f32.f16.f16.f32 "
        "{%0,%1,%2,%3}, {%4,%5,%6,%7}, {%8,%9}, {%0,%1,%2,%3};"
        : "+f"(c[0]), "+f"(c[1]), "+f"(c[2]), "+f"(c[3])
        : "r"(a[0]), "r"(a[1]), "r"(a[2]), "r"(a[3]), "r"(b[0]), "r"(b[1]));
}

__device__ __forceinline__ void cpa16(uint32_t dst, const void* src) {
    asm volatile("cp.async.cg.shared.global [%0], [%1], 16;" :: "r"(dst), "l"(src) : "memory");
}

// vectorized f32 reduction (PTX ISA 8.1, sm_90+)
__device__ __forceinline__ void red2(float* addr, float a, float b) {
    asm volatile("red.global.add.v2.f32 [%0], {%1, %2};" :: "l"(addr), "f"(a), "f"(b) : "memory");
}

__device__ __forceinline__ uint32_t pk_h2(float a, float b) {
    __half2 t = __floats2half2_rn(a, b);
    return reinterpret_cast<uint32_t&>(t);
}

// ---------------- small utility kernels ----------------
__global__ void clear_f4_kernel(float4* p, long long n4) {
    long long i = (long long)blockIdx.x * blockDim.x + threadIdx.x;
    long long stride = (long long)gridDim.x * blockDim.x;
    float4 z = make_float4(0.f, 0.f, 0.f, 0.f);
    for (; i < n4; i += stride) p[i] = z;
}

__global__ void clear_counts_kernel() {
    int i = threadIdx.x;
    if (i < 4) { g_cnt[i] = 0; g_cur[i] = 0; }
}

__global__ void count_types_kernel(const int* __restrict__ etype, int E) {
    int e = blockIdx.x * blockDim.x + threadIdx.x;
    if (e < E) atomicAdd(&g_cnt[etype[e] - 1], 1);
}

__global__ void offsets_kernel() {
    if (threadIdx.x == 0) {
        g_off[0] = 0;
        g_off[1] = g_cnt[0];
        g_off[2] = g_cnt[0] + g_cnt[1];
        g_off[3] = g_cnt[0] + g_cnt[1] + g_cnt[2];
    }
}

__global__ void scatter_types_kernel(const int* __restrict__ etype, int E) {
    int e = blockIdx.x * blockDim.x + threadIdx.x;
    if (e < E) {
        int t = etype[e] - 1;
        int p = atomicAdd(&g_cur[t], 1);
        g_typeEdges[g_off[t] + p] = e;
    }
}

// weights: fp32 -> fp16 hi + fp16 lo (residual)
__global__ void conv_f16_kernel(const float* __restrict__ w, __half* __restrict__ hi,
                                __half* __restrict__ lo, int n) {
    int i = blockIdx.x * blockDim.x + threadIdx.x;
    if (i >= n) return;
    float x = w[i];
    __half h = __float2half_rn(x);
    hi[i] = h;
    lo[i] = __float2half_rn(x - __half2float(h));
}

// state: fp32 -> single fp16
__global__ void tof16_kernel(const float4* __restrict__ S, uint2* __restrict__ Sh, long long n4) {
    long long i = (long long)blockIdx.x * blockDim.x + threadIdx.x;
    if (i >= n4) return;
    float4 v = S[i];
    Sh[i] = make_uint2(pk_h2(v.x, v.y), pk_h2(v.z, v.w));
}

__global__ void embed_kernel(const float4* __restrict__ tab, const int* __restrict__ ids,
                             float4* __restrict__ outS, int N) {
    int idx = blockIdx.x * blockDim.x + threadIdx.x;
    if (idx >= N * 64) return;
    int node = idx >> 6, c = idx & 63;
    int r = ids[node];
    outS[(size_t)node * 64 + c] = tab[(size_t)r * 64 + c];
}

// concat [save(256) | x(256)] -> 512-wide fp16 state
__global__ void concat_f16_kernel(const float4* __restrict__ save, const float4* __restrict__ x,
                                  __half* __restrict__ Sh, int N) {
    int idx = blockIdx.x * blockDim.x + threadIdx.x;
    if (idx >= N * 128) return;
    int node = idx >> 7, c = idx & 127;
    float4 v = (c < 64) ? save[(size_t)node * 64 + c] : x[(size_t)node * 64 + (c - 64)];
    ((uint2*)(Sh + (size_t)node * 512))[c] = make_uint2(pk_h2(v.x, v.y), pk_h2(v.z, v.w));
}

// gelu + layernorm; emits fp16 directly
__global__ void gelu_ln_kernel(const float* __restrict__ M, const float* __restrict__ s,
                               const float* __restrict__ b,
                               __half* __restrict__ Mh, int dm, int N) {
    int warp = (blockIdx.x * blockDim.x + threadIdx.x) >> 5;
    int lane = threadIdx.x & 31;
    if (warp >= N) return;
    const float* row = M + (size_t)warp * dm;
    int per = dm >> 5;
    float v[16];
    float sum = 0.f;
    for (int i = 0; i < per; i++) {
        float x = row[i * 32 + lane];
        float g = 0.5f * x * (1.0f + erff(x * 0.70710678118654752f));
        v[i] = g; sum += g;
    }
    #pragma unroll
    for (int o = 16; o > 0; o >>= 1) sum += __shfl_xor_sync(0xFFFFFFFF, sum, o);
    float mu = sum / (float)dm;
    float vs = 0.f;
    for (int i = 0; i < per; i++) { float d = v[i] - mu; vs += d * d; }
    #pragma unroll
    for (int o = 16; o > 0; o >>= 1) vs += __shfl_xor_sync(0xFFFFFFFF, vs, o);
    float inv = rsqrtf(vs / (float)dm + 1e-5f);
    for (int i = 0; i < per; i++) {
        int c = i * 32 + lane;
        float y = (v[i] - mu) * inv * s[c] + b[c];
        Mh[(size_t)warp * dm + c] = __float2half_rn(y);
    }
}

// ---------------- mma.sync GEMM (MODE 0: edge gather+scatter, MODE 1: dense+tanh) ----------------
// fp16 2-term: C = A_f16 @ (Bh + Bl).  CTA tile 128(M) x 256(N), K chunk 32.
// 512 threads = 16 warps (2x8), warp tile 64x32. 4-stage cp.async pipeline,
// single-chunk mainloop (prefetch distance 3): load target buffer was consumed
// in the PREVIOUS iteration, so the iteration-start barrier protects it.

#define ROWB 80
#define BOFF 10240          // B hi offset (A = 128*80)
#define BSPL 20480          // B lo relative offset (256*80)
#define STAGE 51200
#define NSTAGE 4
#define SMEM_BYTES (1024 + NSTAGE * STAGE)

template<int MODE>
__global__ __launch_bounds__(512, 1)
void mma_gemm(const __half* __restrict__ Ah, int strideA, int K,
              const __half* __restrict__ Bh_, const __half* __restrict__ Bl_,
              int dout, float* __restrict__ Out,
              const int* __restrict__ src, const int* __restrict__ tgt,
              const float* __restrict__ bias, int Nrows,
              __half* __restrict__ OutH) {
    extern __shared__ char smem[];
    int tid = threadIdx.x;
    int wid = tid >> 5, lane = tid & 31;
    int row0 = blockIdx.x * 128;
    int col0 = blockIdx.z * 256;

    const __half *Bh, *Bl;
    int cnt = 0, offT = 0;
    if (MODE == 0) {
        int t = blockIdx.y;
        cnt = g_cnt[t];
        if (row0 >= cnt) return;
        offT = g_off[t];
        Bh = Bh_ + (size_t)t * dout * K;
        Bl = Bl_ + (size_t)t * dout * K;
    } else {
        if (row0 >= Nrows) return;
        Bh = Bh_; Bl = Bl_;
    }

    int* sSrc = (int*)smem;
    int* sTgt = (int*)(smem + 512);
    char* tiles = smem + 1024;
    uint32_t sb = smem_u32(tiles);

    if (MODE == 0 && tid < 128) {
        int r = row0 + tid;
        int sn = 0, tn = -1;
        if (r < cnt) { int e = g_typeEdges[offT + r]; sn = src[e]; tn = tgt[e]; }
        sSrc[tid] = sn; sTgt[tid] = tn;
    }
    __syncthreads();

    // ---- ldmatrix base addresses ----
    int warp_m = wid >> 3, warp_n = wid & 7;
    uint32_t aAddr[4], bAddr[2];
    {
        int r = (lane & 15), hi8 = (lane >> 4) & 1;
        #pragma unroll
        for (int mt = 0; mt < 4; mt++)
            aAddr[mt] = sb + (warp_m * 64 + mt * 16 + r) * ROWB + hi8 * 16;
        int nr = hi8 * 8 + (lane & 7), kq = (lane >> 3) & 1;
        #pragma unroll
        for (int g = 0; g < 2; g++)
            bAddr[g] = sb + BOFF + (warp_n * 32 + g * 16 + nr) * ROWB + kq * 16;
    }

    float acc[4][4][4];
    #pragma unroll
    for (int i = 0; i < 4; i++)
        #pragma unroll
        for (int j = 0; j < 4; j++)
            #pragma unroll
            for (int q = 0; q < 4; q++) acc[i][j][q] = 0.f;

    const int nch = K >> 5;   // K in {256,512,1024} -> nch in {8,16,32}

    // ---- async chunk loader ----
    auto load_chunk = [&](int c) {
        int kt = c * 32;
        uint32_t stg = sb + (c % NSTAGE) * STAGE;
        bool useSrc = true; int colb = kt;
        if (MODE == 0) { useSrc = kt < strideA; colb = useSrc ? kt : kt - strideA; }
        // A: 128 rows x 64B = 512 x 16B (single fp16)
        {
            int m = tid >> 2, u = tid & 3;
            const __half* srcp;
            if (MODE == 0) {
                int node = useSrc ? sSrc[m] : sTgt[m];
                if (node < 0) node = 0;
                srcp = Ah + (size_t)node * strideA + colb + u * 8;
            } else {
                int r = row0 + m; if (r >= Nrows) r = 0;
                srcp = Ah + (size_t)r * strideA + kt + u * 8;
            }
            cpa16(stg + m * ROWB + u * 16, srcp);
        }
        // B hi/lo: 2 x 256 rows x 64B = 2048 x 16B
        #pragma unroll
        for (int i = 0; i < 4; i++) {
            int slot = tid + i * 512;
            int split = slot >> 10, s2 = slot & 1023;
            int n = s2 >> 2, u = s2 & 3;
            const __half* bs = split ? Bl : Bh;
            cpa16(stg + BOFF + split * BSPL + n * ROWB + u * 16,
                  bs + (size_t)(col0 + n) * K + kt + u * 8);
        }
        asm volatile("cp.async.commit_group;" ::: "memory");
    };

    // prologue: stage 3 chunks (prefetch distance 3, 4 buffers)
    load_chunk(0);
    load_chunk(1);
    load_chunk(2);

    for (int c = 0; c < nch; c++) {
        asm volatile("cp.async.wait_group 2;" ::: "memory");   // chunk c complete
        __syncthreads();                                       // visibility + buffer reuse guard
        if (c + 3 < nch) load_chunk(c + 3);                    // buffer (c+3)%4 = (c-1)%4: consumed last iter
        else asm volatile("cp.async.commit_group;" ::: "memory");  // empty group keeps count stable

        uint32_t stoff = (c % NSTAGE) * STAGE;
        #pragma unroll
        for (int ks = 0; ks < 2; ks++) {
            uint32_t ko = stoff + ks * 32;
            uint32_t bhf[2][4], blf[2][4];
            ldm_x4(bAddr[0] + ko, bhf[0]);
            ldm_x4(bAddr[1] + ko, bhf[1]);
            ldm_x4(bAddr[0] + ko + BSPL, blf[0]);
            ldm_x4(bAddr[1] + ko + BSPL, blf[1]);
            #pragma unroll
            for (int mt = 0; mt < 4; mt++) {
                uint32_t ah[4];
                ldm_x4(aAddr[mt] + ko, ah);
                #pragma unroll
                for (int nt = 0; nt < 4; nt++) {
                    const uint32_t* ph = &bhf[nt >> 1][(nt & 1) * 2];
                    const uint32_t* pl = &blf[nt >> 1][(nt & 1) * 2];
                    mma16816(acc[mt][nt], ah, ph);
                    mma16816(acc[mt][nt], ah, pl);
                }
            }
        }
    }

    // ---- epilogue ----
    #pragma unroll
    for (int mt = 0; mt < 4; mt++) {
        int rl = warp_m * 64 + mt * 16 + (lane >> 2);
        int rh = rl + 8;
        if (MODE == 0) {
            int v1 = sTgt[rl], v2 = sTgt[rh];
            #pragma unroll
            for (int nt = 0; nt < 4; nt++) {
                int c = col0 + warp_n * 32 + nt * 8 + 2 * (lane & 3);
                if (v1 >= 0) red2(&Out[(size_t)v1 * dout + c], acc[mt][nt][0], acc[mt][nt][1]);
                if (v2 >= 0) red2(&Out[(size_t)v2 * dout + c], acc[mt][nt][2], acc[mt][nt][3]);
            }
        } else {
            int g1 = row0 + rl, g2 = row0 + rh;
            #pragma unroll
            for (int nt = 0; nt < 4; nt++) {
                int c = col0 + warp_n * 32 + nt * 8 + 2 * (lane & 3);
                float b0 = bias[c], b1 = bias[c + 1];
                if (g1 < Nrows) {
                    float y0 = tanhf(acc[mt][nt][0] + b0);
                    float y1 = tanhf(acc[mt][nt][1] + b1);
                    if (Out) {
                        Out[(size_t)g1 * dout + c]     = y0;
                        Out[(size_t)g1 * dout + c + 1] = y1;
                    }
                    if (OutH) *(uint32_t*)(OutH + (size_t)g1 * dout + c) = pk_h2(y0, y1);
                }
                if (g2 < Nrows) {
                    float y0 = tanhf(acc[mt][nt][2] + b0);
                    float y1 = tanhf(acc[mt][nt][3] + b1);
                    if (Out) {
                        Out[(size_t)g2 * dout + c]     = y0;
                        Out[(size_t)g2 * dout + c + 1] = y1;
                    }
                    if (OutH) *(uint32_t*)(OutH + (size_t)g2 * dout + c) = pk_h2(y0, y1);
                }
            }
        }
    }
}

// ---------------- host-side driver ----------------
static void run_gnn_layer(int din, int N, int E,
                          __half* Sh, __half* Mh,
                          const __half* Weh, const __half* Wel,
                          const float* ls, const float* lb,
                          const __half* Wdh, const __half* Wdl,
                          const float* bias, float* destF, float* Mbuf,
                          __half* destH,
                          const int* src, const int* tgt) {
    long long n4 = (long long)N * din / 4;
    clear_f4_kernel<<<4096, 256>>>((float4*)Mbuf, n4);
    dim3 egrid((E + 127) / 128, 4, din > 256 ? din / 256 : 1);
    mma_gemm<0><<<egrid, 512, SMEM_BYTES>>>(Sh, din, 2 * din, Weh, Wel, din, Mbuf,
                                            src, tgt, nullptr, 0, nullptr);
    gelu_ln_kernel<<<(N + 7) / 8, 256>>>(Mbuf, ls, lb, Mh, din, N);
    dim3 dgrid((N + 127) / 128, 1, 1);
    mma_gemm<1><<<dgrid, 512, SMEM_BYTES>>>(Mh, din, din, Wdh, Wdl, 256, destF,
                                            nullptr, nullptr, bias, N, destH);
}

extern "C" void kernel_launch(void* const* d_in, const int* in_sizes, int n_in,
                              void* d_out, int out_size) {
    const int*   ids   = (const int*)d_in[0];
    const int*   te    = (const int*)d_in[1];
    const float* embed = (const float*)d_in[2];
    const float* WeI   = (const float*)d_in[3];
    const float* lsI   = (const float*)d_in[4];
    const float* lbI   = (const float*)d_in[5];
    const float* WdI   = (const float*)d_in[6];
    const float* bdI   = (const float*)d_in[7];
    const float* WeO   = (const float*)d_in[8];
    const float* lsO   = (const float*)d_in[9];
    const float* lbO   = (const float*)d_in[10];
    const float* WdO   = (const float*)d_in[11];
    const float* bdO   = (const float*)d_in[12];
    float* out = (float*)d_out;

    int N = in_sizes[0];
    int E = in_sizes[1] / 3;
    const int* etype = te;
    const int* src   = te + E;
    const int* tgt   = te + 2 * E;

    float *S0, *S1, *M;
    __half *Sh, *Mh;
    __half *WeIh, *WeIl, *WeOh, *WeOl, *WdIh, *WdIl, *WdOh, *WdOl;
    cudaGetSymbolAddress((void**)&S0, g_S0);
    cudaGetSymbolAddress((void**)&S1, g_S1);
    cudaGetSymbolAddress((void**)&M,  g_M);
    cudaGetSymbolAddress((void**)&Sh, g_Sh);
    cudaGetSymbolAddress((void**)&Mh, g_Mh);
    cudaGetSymbolAddress((void**)&WeIh, g_WeI_h);
    cudaGetSymbolAddress((void**)&WeIl, g_WeI_l);
    cudaGetSymbolAddress((void**)&WeOh, g_WeO_h);
    cudaGetSymbolAddress((void**)&WeOl, g_WeO_l);
    cudaGetSymbolAddress((void**)&WdIh, g_WdI_h);
    cudaGetSymbolAddress((void**)&WdIl, g_WdI_l);
    cudaGetSymbolAddress((void**)&WdOh, g_WdO_h);
    cudaGetSymbolAddress((void**)&WdOl, g_WdO_l);

    cudaFuncSetAttribute(mma_gemm<0>, cudaFuncAttributeMaxDynamicSharedMemorySize, SMEM_BYTES);
    cudaFuncSetAttribute(mma_gemm<1>, cudaFuncAttributeMaxDynamicSharedMemorySize, SMEM_BYTES);

    // --- preprocessing ---
    clear_counts_kernel<<<1, 32>>>();
    count_types_kernel<<<(E + 255) / 256, 256>>>(etype, E);
    offsets_kernel<<<1, 1>>>();
    scatter_types_kernel<<<(E + 255) / 256, 256>>>(etype, E);

    int nWeI = 6 * 4 * 256 * 512, nWeO = 2 * 4 * 512 * 1024;
    int nWdI = 6 * 256 * 256,     nWdO = 2 * 256 * 512;
    conv_f16_kernel<<<(nWeI + 255) / 256, 256>>>(WeI, WeIh, WeIl, nWeI);
    conv_f16_kernel<<<(nWeO + 255) / 256, 256>>>(WeO, WeOh, WeOl, nWeO);
    conv_f16_kernel<<<(nWdI + 255) / 256, 256>>>(WdI, WdIh, WdIl, nWdI);
    conv_f16_kernel<<<(nWdO + 255) / 256, 256>>>(WdO, WdOh, WdOl, nWdO);

    embed_kernel<<<(N * 64 + 255) / 256, 256>>>((const float4*)embed, ids, (float4*)S0, N);
    tof16_kernel<<<(N * 64 + 255) / 256, 256>>>((const float4*)S0, (uint2*)Sh,
                                                (long long)N * 64);

    // Buffer dance (no SAVE copy): block-start fp32 lives in S0 for the whole block;
    // inner L1/L2 fp32 outputs are dead (only fp16 twin consumed) -> skipped;
    // inner L3 fp32 -> S1; concat(S0, S1) -> Sh(512); outer fp32 -> S0 (b=0) / out (b=1).
    for (int b = 0; b < 2; b++) {
        for (int i = 0; i < 3; i++) {
            int l = 3 * b + i;
            float* destF = (i == 2) ? S1 : nullptr;
            run_gnn_layer(256, N, E, Sh, Mh,
                          WeIh + (size_t)l * 4 * 256 * 512, WeIl + (size_t)l * 4 * 256 * 512,
                          lsI + (size_t)l * 256, lbI + (size_t)l * 256,
                          WdIh + (size_t)l * 256 * 256, WdIl + (size_t)l * 256 * 256,
                          bdI + (size_t)l * 256,
                          destF, M, Sh, src, tgt);
        }
        concat_f16_kernel<<<(N * 128 + 255) / 256, 256>>>((const float4*)S0,
                                                          (const float4*)S1, Sh, N);
        float* destF = (b == 1) ? out : S0;
        run_gnn_layer(512, N, E, Sh, Mh,
                      WeOh + (size_t)b * 4 * 512 * 1024, WeOl + (size_t)b * 4 * 512 * 1024,
                      lsO + (size_t)b * 512, lbO + (size_t)b * 512,
                      WdOh + (size_t)b * 256 * 512, WdOl + (size_t)b * 256 * 512,
                      bdO + (size_t)b * 256,
                      destF, M,
                      (b == 0) ? Sh : nullptr,
                      src, tgt);
    }
}

// round 10
// speedup vs baseline: 3.6626x; 1.0235x over previous
#include <cuda_runtime.h>
#include <cuda_fp16.h>
#include <math.h>
#include <stdint.h>

#define MAXN 100000
#define MAXE 320000

// ---------------- scratch (device globals; no allocs allowed) ----------------
__device__ __align__(16) float g_S0[(size_t)MAXN * 256];
__device__ __align__(16) float g_S1[(size_t)MAXN * 256];
__device__ __align__(16) float g_M [(size_t)MAXN * 512];

// fp16 state + message (single precision copy; A-side of GEMMs)
__device__ __align__(16) __half g_Sh[(size_t)MAXN * 512];
__device__ __align__(16) __half g_Mh[(size_t)MAXN * 512];

// fp16 hi/lo weight splits (natural [dout][K] layout == col-major B for mma.row.col)
__device__ __align__(16) __half g_WeI_h[6 * 4 * 256 * 512],  g_WeI_l[6 * 4 * 256 * 512];
__device__ __align__(16) __half g_WeO_h[2 * 4 * 512 * 1024], g_WeO_l[2 * 4 * 512 * 1024];
__device__ __align__(16) __half g_WdI_h[6 * 256 * 256],      g_WdI_l[6 * 256 * 256];
__device__ __align__(16) __half g_WdO_h[2 * 256 * 512],      g_WdO_l[2 * 256 * 512];

__device__ int g_typeEdges[MAXE];
__device__ int g_cnt[4], g_off[4], g_cur[4];

// ---------------- helpers ----------------
__device__ __forceinline__ uint32_t smem_u32(const void* p) {
    uint32_t a;
    asm("{ .reg .u64 t; cvta.to.shared.u64 t, %1; cvt.u32.u64 %0, t; }" : "=r"(a) : "l"(p));
    return a;
}

__device__ __forceinline__ void ldm_x4(uint32_t addr, uint32_t r[4]) {
    asm volatile("ldmatrix.sync.aligned.m8n8.x4.shared.b16 {%0,%1,%2,%3}, [%4];"
                 : "=r"(r[0]), "=r"(r[1]), "=r"(r[2]), "=r"(r[3]) : "r"(addr));
}

__device__ __forceinline__ void mma16816(float c[4], const uint32_t a[4], const uint32_t b[2]) {
    asm volatile(
        "mma.sync.aligned.m16n8k16.row.col.f32.f16.f16.f32 "
        "{%0,%1,%2,%3}, {%4,%5,%6,%7}, {%8,%9}, {%0,%1,%2,%3};"
        : "+f"(c[0]), "+f"(c[1]), "+f"(c[2]), "+f"(c[3])
        : "r"(a[0]), "r"(a[1]), "r"(a[2]), "r"(a[3]), "r"(b[0]), "r"(b[1]));
}

__device__ __forceinline__ void cpa16(uint32_t dst, const void* src) {
    asm volatile("cp.async.cg.shared.global [%0], [%1], 16;" :: "r"(dst), "l"(src) : "memory");
}

// vectorized f32 reduction (PTX ISA 8.1, sm_90+)
__device__ __forceinline__ void red2(float* addr, float a, float b) {
    asm volatile("red.global.add.v2.f32 [%0], {%1, %2};" :: "l"(addr), "f"(a), "f"(b) : "memory");
}

__device__ __forceinline__ uint32_t pk_h2(float a, float b) {
    __half2 t = __floats2half2_rn(a, b);
    return reinterpret_cast<uint32_t&>(t);
}

__device__ __forceinline__ float gelu_f(float x) {
    return 0.5f * x * (1.0f + erff(x * 0.70710678118654752f));
}

// ---------------- small utility kernels ----------------
__global__ void clear_f4_kernel(float4* p, long long n4) {
    long long i = (long long)blockIdx.x * blockDim.x + threadIdx.x;
    long long stride = (long long)gridDim.x * blockDim.x;
    float4 z = make_float4(0.f, 0.f, 0.f, 0.f);
    for (; i < n4; i += stride) p[i] = z;
}

__global__ void clear_counts_kernel() {
    int i = threadIdx.x;
    if (i < 4) { g_cnt[i] = 0; g_cur[i] = 0; }
}

// smem block-histogram: 4 global atomics per block instead of 1 per edge
__global__ void count_types_kernel(const int* __restrict__ etype, int E) {
    __shared__ int h[4];
    if (threadIdx.x < 4) h[threadIdx.x] = 0;
    __syncthreads();
    int e = blockIdx.x * blockDim.x + threadIdx.x;
    if (e < E) atomicAdd(&h[etype[e] - 1], 1);
    __syncthreads();
    if (threadIdx.x < 4 && h[threadIdx.x] > 0) atomicAdd(&g_cnt[threadIdx.x], h[threadIdx.x]);
}

__global__ void offsets_kernel() {
    if (threadIdx.x == 0) {
        g_off[0] = 0;
        g_off[1] = g_cnt[0];
        g_off[2] = g_cnt[0] + g_cnt[1];
        g_off[3] = g_cnt[0] + g_cnt[1] + g_cnt[2];
    }
}

// block-batched scatter: in-block rank via smem, one base atomic per (block,type)
__global__ void scatter_types_kernel(const int* __restrict__ etype, int E) {
    __shared__ int h[4], base[4];
    if (threadIdx.x < 4) h[threadIdx.x] = 0;
    __syncthreads();
    int e = blockIdx.x * blockDim.x + threadIdx.x;
    int t = -1, r = 0;
    if (e < E) { t = etype[e] - 1; r = atomicAdd(&h[t], 1); }
    __syncthreads();
    if (threadIdx.x < 4)
        base[threadIdx.x] = h[threadIdx.x] ? atomicAdd(&g_cur[threadIdx.x], h[threadIdx.x]) : 0;
    __syncthreads();
    if (t >= 0) g_typeEdges[g_off[t] + base[t] + r] = e;
}

// weights: fp32 -> fp16 hi + fp16 lo (residual)
__global__ void conv_f16_kernel(const float* __restrict__ w, __half* __restrict__ hi,
                                __half* __restrict__ lo, int n) {
    int i = blockIdx.x * blockDim.x + threadIdx.x;
    if (i >= n) return;
    float x = w[i];
    __half h = __float2half_rn(x);
    hi[i] = h;
    lo[i] = __float2half_rn(x - __half2float(h));
}

// embed + fp16 split fused: one pass over the gathered rows
__global__ void embed_kernel(const float4* __restrict__ tab, const int* __restrict__ ids,
                             float4* __restrict__ outS, uint2* __restrict__ Sh, int N) {
    int idx = blockIdx.x * blockDim.x + threadIdx.x;
    if (idx >= N * 64) return;
    int node = idx >> 6, c = idx & 63;
    int r = ids[node];
    float4 v = tab[(size_t)r * 64 + c];
    outS[(size_t)node * 64 + c] = v;
    Sh[(size_t)node * 64 + c] = make_uint2(pk_h2(v.x, v.y), pk_h2(v.z, v.w));
}

// concat [save(256) | x(256)] -> 512-wide fp16 state
__global__ void concat_f16_kernel(const float4* __restrict__ save, const float4* __restrict__ x,
                                  __half* __restrict__ Sh, int N) {
    int idx = blockIdx.x * blockDim.x + threadIdx.x;
    if (idx >= N * 128) return;
    int node = idx >> 7, c = idx & 127;
    float4 v = (c < 64) ? save[(size_t)node * 64 + c] : x[(size_t)node * 64 + (c - 64)];
    ((uint2*)(Sh + (size_t)node * 512))[c] = make_uint2(pk_h2(v.x, v.y), pk_h2(v.z, v.w));
}

// gelu + layernorm; float4-vectorized; emits fp16 directly
__global__ void gelu_ln_kernel(const float4* __restrict__ M, const float4* __restrict__ s4,
                               const float4* __restrict__ b4,
                               uint2* __restrict__ Mh, int dm, int N) {
    int warp = (blockIdx.x * blockDim.x + threadIdx.x) >> 5;
    int lane = threadIdx.x & 31;
    if (warp >= N) return;
    int n4 = dm >> 2;             // float4 per row: 64 or 128
    int per = n4 >> 5;            // float4 per lane: 2 or 4
    const float4* row = M + (size_t)warp * n4;
    float4 v[4];
    float sum = 0.f;
    for (int i = 0; i < per; i++) {
        float4 x = row[i * 32 + lane];
        float4 g;
        g.x = gelu_f(x.x); g.y = gelu_f(x.y); g.z = gelu_f(x.z); g.w = gelu_f(x.w);
        v[i] = g;
        sum += g.x + g.y + g.z + g.w;
    }
    #pragma unroll
    for (int o = 16; o > 0; o >>= 1) sum += __shfl_xor_sync(0xFFFFFFFF, sum, o);
    float mu = sum / (float)dm;
    float vs = 0.f;
    for (int i = 0; i < per; i++) {
        float dx = v[i].x - mu, dy = v[i].y - mu, dz = v[i].z - mu, dw = v[i].w - mu;
        vs += dx * dx + dy * dy + dz * dz + dw * dw;
    }
    #pragma unroll
    for (int o = 16; o > 0; o >>= 1) vs += __shfl_xor_sync(0xFFFFFFFF, vs, o);
    float inv = rsqrtf(vs / (float)dm + 1e-5f);
    for (int i = 0; i < per; i++) {
        int c4 = i * 32 + lane;
        float4 sv = s4[c4], bv = b4[c4];
        float y0 = (v[i].x - mu) * inv * sv.x + bv.x;
        float y1 = (v[i].y - mu) * inv * sv.y + bv.y;
        float y2 = (v[i].z - mu) * inv * sv.z + bv.z;
        float y3 = (v[i].w - mu) * inv * sv.w + bv.w;
        Mh[(size_t)warp * n4 + c4] = make_uint2(pk_h2(y0, y1), pk_h2(y2, y3));
    }
}

// ---------------- mma.sync GEMM (MODE 0: edge gather+scatter, MODE 1: dense+tanh) ----------------
// fp16 2-term: C = A_f16 @ (Bh + Bl).  CTA tile 128(M) x 256(N), K chunk 32.
// 512 threads = 16 warps (2x8), warp tile 64x32. 4-stage cp.async pipeline,
// single-chunk mainloop (prefetch distance 3): load target buffer was consumed
// in the PREVIOUS iteration, so the iteration-start barrier protects it.

#define ROWB 80
#define BOFF 10240          // B hi offset (A = 128*80)
#define BSPL 20480          // B lo relative offset (256*80)
#define STAGE 51200
#define NSTAGE 4
#define SMEM_BYTES (1024 + NSTAGE * STAGE)

template<int MODE>
__global__ __launch_bounds__(512, 1)
void mma_gemm(const __half* __restrict__ Ah, int strideA, int K,
              const __half* __restrict__ Bh_, const __half* __restrict__ Bl_,
              int dout, float* __restrict__ Out,
              const int* __restrict__ src, const int* __restrict__ tgt,
              const float* __restrict__ bias, int Nrows,
              __half* __restrict__ OutH) {
    extern __shared__ char smem[];
    int tid = threadIdx.x;
    int wid = tid >> 5, lane = tid & 31;
    int row0 = blockIdx.x * 128;
    int col0 = blockIdx.z * 256;

    const __half *Bh, *Bl;
    int cnt = 0, offT = 0;
    if (MODE == 0) {
        int t = blockIdx.y;
        cnt = g_cnt[t];
        if (row0 >= cnt) return;
        offT = g_off[t];
        Bh = Bh_ + (size_t)t * dout * K;
        Bl = Bl_ + (size_t)t * dout * K;
    } else {
        if (row0 >= Nrows) return;
        Bh = Bh_; Bl = Bl_;
    }

    int* sSrc = (int*)smem;
    int* sTgt = (int*)(smem + 512);
    char* tiles = smem + 1024;
    uint32_t sb = smem_u32(tiles);

    if (MODE == 0 && tid < 128) {
        int r = row0 + tid;
        int sn = 0, tn = -1;
        if (r < cnt) { int e = g_typeEdges[offT + r]; sn = src[e]; tn = tgt[e]; }
        sSrc[tid] = sn; sTgt[tid] = tn;
    }
    __syncthreads();

    // ---- ldmatrix base addresses ----
    int warp_m = wid >> 3, warp_n = wid & 7;
    uint32_t aAddr[4], bAddr[2];
    {
        int r = (lane & 15), hi8 = (lane >> 4) & 1;
        #pragma unroll
        for (int mt = 0; mt < 4; mt++)
            aAddr[mt] = sb + (warp_m * 64 + mt * 16 + r) * ROWB + hi8 * 16;
        int nr = hi8 * 8 + (lane & 7), kq = (lane >> 3) & 1;
        #pragma unroll
        for (int g = 0; g < 2; g++)
            bAddr[g] = sb + BOFF + (warp_n * 32 + g * 16 + nr) * ROWB + kq * 16;
    }

    float acc[4][4][4];
    #pragma unroll
    for (int i = 0; i < 4; i++)
        #pragma unroll
        for (int j = 0; j < 4; j++)
            #pragma unroll
            for (int q = 0; q < 4; q++) acc[i][j][q] = 0.f;

    const int nch = K >> 5;   // K in {256,512,1024} -> nch in {8,16,32}

    // ---- async chunk loader ----
    auto load_chunk = [&](int c) {
        int kt = c * 32;
        uint32_t stg = sb + (c % NSTAGE) * STAGE;
        bool useSrc = true; int colb = kt;
        if (MODE == 0) { useSrc = kt < strideA; colb = useSrc ? kt : kt - strideA; }
        // A: 128 rows x 64B = 512 x 16B (single fp16)
        {
            int m = tid >> 2, u = tid & 3;
            const __half* srcp;
            if (MODE == 0) {
                int node = useSrc ? sSrc[m] : sTgt[m];
                if (node < 0) node = 0;
                srcp = Ah + (size_t)node * strideA + colb + u * 8;
            } else {
                int r = row0 + m; if (r >= Nrows) r = 0;
                srcp = Ah + (size_t)r * strideA + kt + u * 8;
            }
            cpa16(stg + m * ROWB + u * 16, srcp);
        }
        // B hi/lo: 2 x 256 rows x 64B = 2048 x 16B
        #pragma unroll
        for (int i = 0; i < 4; i++) {
            int slot = tid + i * 512;
            int split = slot >> 10, s2 = slot & 1023;
            int n = s2 >> 2, u = s2 & 3;
            const __half* bs = split ? Bl : Bh;
            cpa16(stg + BOFF + split * BSPL + n * ROWB + u * 16,
                  bs + (size_t)(col0 + n) * K + kt + u * 8);
        }
        asm volatile("cp.async.commit_group;" ::: "memory");
    };

    // prologue: stage 3 chunks (prefetch distance 3, 4 buffers)
    load_chunk(0);
    load_chunk(1);
    load_chunk(2);

    for (int c = 0; c < nch; c++) {
        asm volatile("cp.async.wait_group 2;" ::: "memory");   // chunk c complete
        __syncthreads();                                       // visibility + buffer reuse guard
        if (c + 3 < nch) load_chunk(c + 3);                    // buffer (c+3)%4 = (c-1)%4: consumed last iter
        else asm volatile("cp.async.commit_group;" ::: "memory");  // empty group keeps count stable

        uint32_t stoff = (c % NSTAGE) * STAGE;
        #pragma unroll
        for (int ks = 0; ks < 2; ks++) {
            uint32_t ko = stoff + ks * 32;
            uint32_t bhf[2][4], blf[2][4];
            ldm_x4(bAddr[0] + ko, bhf[0]);
            ldm_x4(bAddr[1] + ko, bhf[1]);
            ldm_x4(bAddr[0] + ko + BSPL, blf[0]);
            ldm_x4(bAddr[1] + ko + BSPL, blf[1]);
            #pragma unroll
            for (int mt = 0; mt < 4; mt++) {
                uint32_t ah[4];
                ldm_x4(aAddr[mt] + ko, ah);
                #pragma unroll
                for (int nt = 0; nt < 4; nt++) {
                    const uint32_t* ph = &bhf[nt >> 1][(nt & 1) * 2];
                    const uint32_t* pl = &blf[nt >> 1][(nt & 1) * 2];
                    mma16816(acc[mt][nt], ah, ph);
                    mma16816(acc[mt][nt], ah, pl);
                }
            }
        }
    }

    // ---- epilogue ----
    #pragma unroll
    for (int mt = 0; mt < 4; mt++) {
        int rl = warp_m * 64 + mt * 16 + (lane >> 2);
        int rh = rl + 8;
        if (MODE == 0) {
            int v1 = sTgt[rl], v2 = sTgt[rh];
            #pragma unroll
            for (int nt = 0; nt < 4; nt++) {
                int c = col0 + warp_n * 32 + nt * 8 + 2 * (lane & 3);
                if (v1 >= 0) red2(&Out[(size_t)v1 * dout + c], acc[mt][nt][0], acc[mt][nt][1]);
                if (v2 >= 0) red2(&Out[(size_t)v2 * dout + c], acc[mt][nt][2], acc[mt][nt][3]);
            }
        } else {
            int g1 = row0 + rl, g2 = row0 + rh;
            #pragma unroll
            for (int nt = 0; nt < 4; nt++) {
                int c = col0 + warp_n * 32 + nt * 8 + 2 * (lane & 3);
                float b0 = bias[c], b1 = bias[c + 1];
                if (g1 < Nrows) {
                    float y0 = tanhf(acc[mt][nt][0] + b0);
                    float y1 = tanhf(acc[mt][nt][1] + b1);
                    if (Out) {
                        Out[(size_t)g1 * dout + c]     = y0;
                        Out[(size_t)g1 * dout + c + 1] = y1;
                    }
                    if (OutH) *(uint32_t*)(OutH + (size_t)g1 * dout + c) = pk_h2(y0, y1);
                }
                if (g2 < Nrows) {
                    float y0 = tanhf(acc[mt][nt][2] + b0);
                    float y1 = tanhf(acc[mt][nt][3] + b1);
                    if (Out) {
                        Out[(size_t)g2 * dout + c]     = y0;
                        Out[(size_t)g2 * dout + c + 1] = y1;
                    }
                    if (OutH) *(uint32_t*)(OutH + (size_t)g2 * dout + c) = pk_h2(y0, y1);
                }
            }
        }
    }
}

// ---------------- host-side driver ----------------
static void run_gnn_layer(int din, int N, int E,
                          __half* Sh, __half* Mh,
                          const __half* Weh, const __half* Wel,
                          const float* ls, const float* lb,
                          const __half* Wdh, const __half* Wdl,
                          const float* bias, float* destF, float* Mbuf,
                          __half* destH,
                          const int* src, const int* tgt) {
    long long n4 = (long long)N * din / 4;
    clear_f4_kernel<<<4096, 256>>>((float4*)Mbuf, n4);
    dim3 egrid((E + 127) / 128, 4, din > 256 ? din / 256 : 1);
    mma_gemm<0><<<egrid, 512, SMEM_BYTES>>>(Sh, din, 2 * din, Weh, Wel, din, Mbuf,
                                            src, tgt, nullptr, 0, nullptr);
    gelu_ln_kernel<<<(N + 7) / 8, 256>>>((const float4*)Mbuf, (const float4*)ls,
                                         (const float4*)lb, (uint2*)Mh, din, N);
    dim3 dgrid((N + 127) / 128, 1, 1);
    mma_gemm<1><<<dgrid, 512, SMEM_BYTES>>>(Mh, din, din, Wdh, Wdl, 256, destF,
                                            nullptr, nullptr, bias, N, destH);
}

extern "C" void kernel_launch(void* const* d_in, const int* in_sizes, int n_in,
                              void* d_out, int out_size) {
    const int*   ids   = (const int*)d_in[0];
    const int*   te    = (const int*)d_in[1];
    const float* embed = (const float*)d_in[2];
    const float* WeI   = (const float*)d_in[3];
    const float* lsI   = (const float*)d_in[4];
    const float* lbI   = (const float*)d_in[5];
    const float* WdI   = (const float*)d_in[6];
    const float* bdI   = (const float*)d_in[7];
    const float* WeO   = (const float*)d_in[8];
    const float* lsO   = (const float*)d_in[9];
    const float* lbO   = (const float*)d_in[10];
    const float* WdO   = (const float*)d_in[11];
    const float* bdO   = (const float*)d_in[12];
    float* out = (float*)d_out;

    int N = in_sizes[0];
    int E = in_sizes[1] / 3;
    const int* etype = te;
    const int* src   = te + E;
    const int* tgt   = te + 2 * E;

    float *S0, *S1, *M;
    __half *Sh, *Mh;
    __half *WeIh, *WeIl, *WeOh, *WeOl, *WdIh, *WdIl, *WdOh, *WdOl;
    cudaGetSymbolAddress((void**)&S0, g_S0);
    cudaGetSymbolAddress((void**)&S1, g_S1);
    cudaGetSymbolAddress((void**)&M,  g_M);
    cudaGetSymbolAddress((void**)&Sh, g_Sh);
    cudaGetSymbolAddress((void**)&Mh, g_Mh);
    cudaGetSymbolAddress((void**)&WeIh, g_WeI_h);
    cudaGetSymbolAddress((void**)&WeIl, g_WeI_l);
    cudaGetSymbolAddress((void**)&WeOh, g_WeO_h);
    cudaGetSymbolAddress((void**)&WeOl, g_WeO_l);
    cudaGetSymbolAddress((void**)&WdIh, g_WdI_h);
    cudaGetSymbolAddress((void**)&WdIl, g_WdI_l);
    cudaGetSymbolAddress((void**)&WdOh, g_WdO_h);
    cudaGetSymbolAddress((void**)&WdOl, g_WdO_l);

    cudaFuncSetAttribute(mma_gemm<0>, cudaFuncAttributeMaxDynamicSharedMemorySize, SMEM_BYTES);
    cudaFuncSetAttribute(mma_gemm<1>, cudaFuncAttributeMaxDynamicSharedMemorySize, SMEM_BYTES);

    // --- preprocessing ---
    clear_counts_kernel<<<1, 32>>>();
    count_types_kernel<<<(E + 255) / 256, 256>>>(etype, E);
    offsets_kernel<<<1, 1>>>();
    scatter_types_kernel<<<(E + 255) / 256, 256>>>(etype, E);

    int nWeI = 6 * 4 * 256 * 512, nWeO = 2 * 4 * 512 * 1024;
    int nWdI = 6 * 256 * 256,     nWdO = 2 * 256 * 512;
    conv_f16_kernel<<<(nWeI + 255) / 256, 256>>>(WeI, WeIh, WeIl, nWeI);
    conv_f16_kernel<<<(nWeO + 255) / 256, 256>>>(WeO, WeOh, WeOl, nWeO);
    conv_f16_kernel<<<(nWdI + 255) / 256, 256>>>(WdI, WdIh, WdIl, nWdI);
    conv_f16_kernel<<<(nWdO + 255) / 256, 256>>>(WdO, WdOh, WdOl, nWdO);

    embed_kernel<<<(N * 64 + 255) / 256, 256>>>((const float4*)embed, ids, (float4*)S0,
                                                (uint2*)Sh, N);

    // Buffer dance (no SAVE copy): block-start fp32 lives in S0 for the whole block;
    // inner L1/L2 fp32 outputs are dead (only fp16 twin consumed) -> skipped;
    // inner L3 fp32 -> S1; concat(S0, S1) -> Sh(512); outer fp32 -> S0 (b=0) / out (b=1).
    for (int b = 0; b < 2; b++) {
        for (int i = 0; i < 3; i++) {
            int l = 3 * b + i;
            float* destF = (i == 2) ? S1 : nullptr;
            run_gnn_layer(256, N, E, Sh, Mh,
                          WeIh + (size_t)l * 4 * 256 * 512, WeIl + (size_t)l * 4 * 256 * 512,
                          lsI + (size_t)l * 256, lbI + (size_t)l * 256,
                          WdIh + (size_t)l * 256 * 256, WdIl + (size_t)l * 256 * 256,
                          bdI + (size_t)l * 256,
                          destF, M, Sh, src, tgt);
        }
        concat_f16_kernel<<<(N * 128 + 255) / 256, 256>>>((const float4*)S0,
                                                          (const float4*)S1, Sh, N);
        float* destF = (b == 1) ? out : S0;
        run_gnn_layer(512, N, E, Sh, Mh,
                      WeOh + (size_t)b * 4 * 512 * 1024, WeOl + (size_t)b * 4 * 512 * 1024,
                      lsO + (size_t)b * 512, lbO + (size_t)b * 512,
                      WdOh + (size_t)b * 256 * 512, WdOl + (size_t)b * 256 * 512,
                      bdO + (size_t)b * 256,
                      destF, M,
                      (b == 0) ? Sh : nullptr,
                      src, tgt);
    }
}